// round 9
// baseline (speedup 1.0000x reference)
#include <cuda_runtime.h>
#include <cuda_fp16.h>
#include <math.h>
#include <stdint.h>

#define T_TOK 8192
#define D_DIM 1024
#define F_DIM 4096
#define E_EXP 8

// ---------------- scratch (static device globals; no allocations) ----------
__device__ int    g_cnt[E_EXP];
__device__ int    g_off[E_EXP];
__device__ int    g_tok[E_EXP * T_TOK];
__device__ float  g_wt [E_EXP * T_TOK];

__device__ __half g_xh [(size_t)T_TOK * D_DIM];
__device__ __half g_w1h[(size_t)E_EXP * F_DIM * D_DIM];
__device__ __half g_w2h[(size_t)E_EXP * D_DIM * F_DIM];
__device__ __half g_hh [(size_t)2 * T_TOK * F_DIM];

// ---------------- PTX helpers (sm_80+ features only) ------------------------
__device__ __forceinline__ uint32_t smem_u32(const void* p) {
    uint32_t a;
    asm("{ .reg .u64 t; cvta.to.shared.u64 t, %1; cvt.u32.u64 %0, t; }" : "=r"(a) : "l"(p));
    return a;
}
#define CP16(dst, src) asm volatile("cp.async.cg.shared.global [%0], [%1], 16;" :: "r"(dst), "l"(src) : "memory")
#define CP_COMMIT()    asm volatile("cp.async.commit_group;" ::: "memory")
#define CP_WAIT(n)     asm volatile("cp.async.wait_group %0;" :: "n"(n) : "memory")
#define LDX4(r, a)                                                             \
    asm volatile("ldmatrix.sync.aligned.m8n8.x4.shared.b16 {%0,%1,%2,%3}, [%4];" \
        : "=r"((r)[0]), "=r"((r)[1]), "=r"((r)[2]), "=r"((r)[3]) : "r"(a))
#define MMAH(d, a, b0, b1)                                                     \
    asm volatile("mma.sync.aligned.m16n8k16.row.col.f32.f16.f16.f32 "          \
        "{%0,%1,%2,%3},{%4,%5,%6,%7},{%8,%9},{%0,%1,%2,%3};"                   \
        : "+f"((d)[0]), "+f"((d)[1]), "+f"((d)[2]), "+f"((d)[3])               \
        : "r"((a)[0]), "r"((a)[1]), "r"((a)[2]), "r"((a)[3]), "r"(b0), "r"(b1))

__device__ __forceinline__ uint32_t pack_h(__half a, __half b) {
    return ((uint32_t)__half_as_ushort(b) << 16) | __half_as_ushort(a);
}

// SMEM: toks @0 (512B), bias @512 (1024B, 256 f32), wts @1536 (512B), stages @2048.
// Stage (k-chunk 64 fp16 = 128B, pitch 144B): A @0 (128x144=18432), B @18432 (256x144).
#define SM_HDR  2048
#define PITCH   144
#define STG_SZ  55296
#define NSTAGE  3
#define SMEM_DYN (SM_HDR + NSTAGE * STG_SZ)

// ---------------- init ------------------------------------------------------
__global__ void k_init(float4* __restrict__ out4) {
    int i = blockIdx.x * blockDim.x + threadIdx.x;
    if (i < E_EXP) g_cnt[i] = 0;
    const size_t n4 = (size_t)T_TOK * D_DIM / 4;
    float4 z = make_float4(0.f, 0.f, 0.f, 0.f);
    for (size_t j = i; j < n4; j += (size_t)gridDim.x * blockDim.x) out4[j] = z;
}

// ---------------- convert fp32 -> fp16 ---------------------------------------
__global__ void k_split(const float* __restrict__ x, const float* __restrict__ w1,
                        const float* __restrict__ w2) {
    size_t stride = (size_t)gridDim.x * blockDim.x;
    size_t i0 = (size_t)blockIdx.x * blockDim.x + threadIdx.x;
    const size_t nx4 = (size_t)T_TOK * D_DIM / 4;
    const size_t nw4 = (size_t)E_EXP * F_DIM * D_DIM / 4;
    uint2* xo  = (uint2*)g_xh;
    uint2* w1o = (uint2*)g_w1h;
    uint2* w2o = (uint2*)g_w2h;
    for (size_t i = i0; i < nx4; i += stride) {
        float4 f = ((const float4*)x)[i];
        xo[i] = make_uint2(pack_h(__float2half_rn(f.x), __float2half_rn(f.y)),
                           pack_h(__float2half_rn(f.z), __float2half_rn(f.w)));
    }
    for (size_t i = i0; i < nw4; i += stride) {
        float4 f = ((const float4*)w1)[i];
        w1o[i] = make_uint2(pack_h(__float2half_rn(f.x), __float2half_rn(f.y)),
                            pack_h(__float2half_rn(f.z), __float2half_rn(f.w)));
    }
    for (size_t i = i0; i < nw4; i += stride) {
        float4 f = ((const float4*)w2)[i];
        w2o[i] = make_uint2(pack_h(__float2half_rn(f.x), __float2half_rn(f.y)),
                            pack_h(__float2half_rn(f.z), __float2half_rn(f.w)));
    }
}

// ---------------- gating (validated) ----------------------------------------
__global__ void k_gate(const float* __restrict__ x, const float* __restrict__ gw,
                       float* __restrict__ probs_out) {
    int warp = (blockIdx.x * blockDim.x + threadIdx.x) >> 5;
    int lane = threadIdx.x & 31;
    if (warp >= T_TOK) return;
    const float* xr = x + (size_t)warp * D_DIM;
    float acc[E_EXP];
#pragma unroll
    for (int e = 0; e < E_EXP; e++) acc[e] = 0.f;
    for (int k = lane * 4; k < D_DIM; k += 128) {
        float4 xv = *(const float4*)(xr + k);
#pragma unroll
        for (int e = 0; e < E_EXP; e++) {
            float4 wv = *(const float4*)(gw + (size_t)e * D_DIM + k);
            acc[e] += xv.x * wv.x + xv.y * wv.y + xv.z * wv.z + xv.w * wv.w;
        }
    }
#pragma unroll
    for (int e = 0; e < E_EXP; e++)
#pragma unroll
        for (int o = 16; o > 0; o >>= 1) acc[e] += __shfl_xor_sync(0xffffffffu, acc[e], o);
    if (lane == 0) {
        float mx = acc[0];
#pragma unroll
        for (int e = 1; e < E_EXP; e++) mx = fmaxf(mx, acc[e]);
        float p[E_EXP], s = 0.f;
#pragma unroll
        for (int e = 0; e < E_EXP; e++) { p[e] = expf(acc[e] - mx); s += p[e]; }
        float inv = 1.f / s;
#pragma unroll
        for (int e = 0; e < E_EXP; e++) {
            p[e] *= inv;
            probs_out[(size_t)warp * E_EXP + e] = p[e];
        }
        int i0 = 0;
#pragma unroll
        for (int e = 1; e < E_EXP; e++) if (p[e] > p[i0]) i0 = e;
        int i1 = (i0 == 0) ? 1 : 0;
#pragma unroll
        for (int e = 0; e < E_EXP; e++) if (e != i0 && p[e] > p[i1]) i1 = e;
        float denom = p[i0] + p[i1] + 1e-9f;
        int s0 = atomicAdd(&g_cnt[i0], 1);
        g_tok[i0 * T_TOK + s0] = warp; g_wt[i0 * T_TOK + s0] = p[i0] / denom;
        int s1 = atomicAdd(&g_cnt[i1], 1);
        g_tok[i1 * T_TOK + s1] = warp; g_wt[i1 * T_TOK + s1] = p[i1] / denom;
    }
}
__global__ void k_prefix() {
    if (threadIdx.x == 0) {
        int run = 0;
#pragma unroll
        for (int e = 0; e < E_EXP; e++) { g_off[e] = run; run += g_cnt[e]; }
    }
}

// ---------------- GEMM core: block 128x256xk64, 8 warps, warp 64x64 ---------
// 32 LDX4 : 128 MMA per warp-chunk (0.25/MMA vs 0.375 before).
#define LDM_SETUP()                                                            \
    const int lane = tid & 31, wid = tid >> 5;                                 \
    const int wm = (wid & 1) * 64, wn = (wid >> 1) * 64;                       \
    uint32_t aav[4];                                                           \
    _Pragma("unroll") for (int mt = 0; mt < 4; ++mt)                           \
        aav[mt] = sb + SM_HDR + (wm + mt * 16 + (lane & 15)) * PITCH +         \
                  ((lane >> 4) & 1) * 16;                                      \
    uint32_t bbv[4];                                                           \
    _Pragma("unroll") for (int g = 0; g < 4; ++g)                              \
        bbv[g] = sb + SM_HDR + 18432 +                                         \
            (wn + g * 16 + (lane & 7) + ((lane >> 4) & 1) * 8) * PITCH +       \
            ((lane >> 3) & 1) * 16;

// Fragment-pipelined: B group g+1 prefetched during g's MMAs; A chunk kk+1
// prefetched during g=0,1. Per-accumulator MMA order identical => bit-identical.
#define CHUNK(so) {                                                            \
    uint32_t Ah[2][4][4], Bh[2][4];                                            \
    _Pragma("unroll") for (int mt = 0; mt < 4; ++mt) LDX4(Ah[0][mt], aav[mt] + (so)); \
    LDX4(Bh[0], bbv[0] + (so));                                                \
    _Pragma("unroll") for (int kk = 0; kk < 4; ++kk) {                         \
        _Pragma("unroll") for (int g = 0; g < 4; ++g) {                        \
            const int cur = g & 1, nxt = cur ^ 1;                              \
            if (g < 3)       { LDX4(Bh[nxt], bbv[g + 1] + (so) + kk * 32); }   \
            else if (kk < 3) { LDX4(Bh[nxt], bbv[0] + (so) + (kk + 1) * 32); } \
            if (kk < 3 && g < 2) {                                             \
                LDX4(Ah[(kk + 1) & 1][2 * g],     aav[2 * g]     + (so) + (kk + 1) * 32); \
                LDX4(Ah[(kk + 1) & 1][2 * g + 1], aav[2 * g + 1] + (so) + (kk + 1) * 32); \
            }                                                                  \
            _Pragma("unroll") for (int mt = 0; mt < 4; ++mt)                   \
                MMAH(acc[mt][2 * g],     Ah[kk & 1][mt], Bh[cur][0], Bh[cur][1]); \
            _Pragma("unroll") for (int mt = 0; mt < 4; ++mt)                   \
                MMAH(acc[mt][2 * g + 1], Ah[kk & 1][mt], Bh[cur][2], Bh[cur][3]); \
        }                                                                      \
    }                                                                          \
}

#define ACC_INIT()                                                             \
    float acc[4][8][4];                                                        \
    _Pragma("unroll") for (int i = 0; i < 4; i++)                              \
        _Pragma("unroll") for (int j = 0; j < 8; j++)                          \
            _Pragma("unroll") for (int k = 0; k < 4; k++) acc[i][j][k] = 0.f;

// ---------------- fc1: h = gelu(X[gather] @ W1e^T + b1) -> fp16 -------------
__global__ __launch_bounds__(256, 1) void k_fc1_h(const float* __restrict__ b1) {
    const int e = blockIdx.z;
    const int cnt = g_cnt[e];
    const int m0 = blockIdx.y * 128;
    if (m0 >= cnt) return;
    const int n0 = blockIdx.x * 256;

    extern __shared__ __align__(128) char smp[];
    const uint32_t sb = smem_u32(smp);
    int*   toks_s = (int*)smp;
    float* bias_s = (float*)(smp + 512);
    const int tid = threadIdx.x;
    if (tid < 128) toks_s[tid] = g_tok[e * T_TOK + min(m0 + tid, cnt - 1)];
    bias_s[tid] = b1[e * F_DIM + n0 + tid];
    __syncthreads();

    // staging: q = tid&7 (16B quad of 128B row), r = tid>>3 (0..31)
    const int q = tid & 7, r = tid >> 3;
    const uint32_t dA = sb + SM_HDR + r * PITCH + q * 16;
    const uint32_t dB = dA + 18432;
    const char* xp = (const char*)g_xh;
    size_t aoff[4];
#pragma unroll
    for (int j = 0; j < 4; ++j)
        aoff[j] = (size_t)toks_s[r + 32 * j] * (D_DIM * 2) + q * 16;
    const char* wpb = (const char*)(g_w1h + ((size_t)e * F_DIM + n0 + r) * D_DIM) + q * 16;

#define STAGE1(c, so) { const uint32_t ko = (uint32_t)(c) * 128;               \
    _Pragma("unroll") for (int j = 0; j < 4; ++j)                              \
        CP16(dA + (so) + j * (32 * PITCH), xp + aoff[j] + ko);                 \
    _Pragma("unroll") for (int j = 0; j < 8; ++j)                              \
        CP16(dB + (so) + j * (32 * PITCH), wpb + (size_t)j * (32 * D_DIM * 2) + ko); \
    CP_COMMIT(); }

    LDM_SETUP();
    ACC_INIT();

    const int NC = D_DIM / 64;  // 16
    STAGE1(0, 0); STAGE1(1, STG_SZ);
    for (int c = 0; c < NC; ++c) {
        if (c + 1 < NC) { CP_WAIT(1); } else { CP_WAIT(0); }
        __syncthreads();
        if (c + 2 < NC) {
            const int cn = c + 2;
            STAGE1(cn, (uint32_t)(cn % 3) * STG_SZ);
        }
        CHUNK((uint32_t)(c % 3) * STG_SZ);
    }

    // epilogue: bias + exact gelu -> fp16 -> g_hh
    const int gid2 = lane >> 2, tg = lane & 3;
    const int hbase = g_off[e] + m0;
    uint32_t* gh = (uint32_t*)g_hh;
#pragma unroll
    for (int mt = 0; mt < 4; ++mt)
#pragma unroll
        for (int nt = 0; nt < 8; ++nt) {
            const int n = wn + nt * 8 + tg * 2;
            const float bv0 = bias_s[n], bv1 = bias_s[n + 1];
#pragma unroll
            for (int h = 0; h < 2; ++h) {
                const int m = wm + mt * 16 + gid2 + h * 8;
                if (m0 + m < cnt) {
                    float v0 = acc[mt][nt][2 * h + 0] + bv0;
                    float v1 = acc[mt][nt][2 * h + 1] + bv1;
                    v0 = 0.5f * v0 * (1.f + erff(v0 * 0.7071067811865476f));
                    v1 = 0.5f * v1 * (1.f + erff(v1 * 0.7071067811865476f));
                    gh[(size_t)(hbase + m) * (F_DIM / 2) + (size_t)(n0 + n) / 2] =
                        pack_h(__float2half_rn(v0), __float2half_rn(v1));
                }
            }
        }
}

// ---------------- fc2: out[tok] += w * (H @ W2e^T + b2) ---------------------
__global__ __launch_bounds__(256, 1) void k_fc2_h(const float* __restrict__ b2,
                                                  float* __restrict__ out) {
    const int e = blockIdx.z;
    const int cnt = g_cnt[e];
    const int m0 = blockIdx.y * 128;
    if (m0 >= cnt) return;
    const int n0 = blockIdx.x * 256;

    extern __shared__ __align__(128) char smp[];
    const uint32_t sb = smem_u32(smp);
    int*   toks_s = (int*)smp;
    float* bias_s = (float*)(smp + 512);
    float* wts_s  = (float*)(smp + 1536);
    const int tid = threadIdx.x;
    if (tid < 128) {
        const int sl = min(m0 + tid, cnt - 1);
        toks_s[tid] = g_tok[e * T_TOK + sl];
        wts_s[tid]  = g_wt [e * T_TOK + sl];
    }
    bias_s[tid] = b2[e * D_DIM + n0 + tid];
    __syncthreads();

    const int q = tid & 7, r = tid >> 3;
    const uint32_t dA = sb + SM_HDR + r * PITCH + q * 16;
    const uint32_t dB = dA + 18432;
    const char* hp = (const char*)g_hh;
    size_t aoff[4];
#pragma unroll
    for (int j = 0; j < 4; ++j)
        aoff[j] = (size_t)(g_off[e] + min(m0 + r + 32 * j, cnt - 1)) * (F_DIM * 2) + q * 16;
    const char* wpb = (const char*)(g_w2h + ((size_t)e * D_DIM + n0 + r) * F_DIM) + q * 16;

#define STAGE2(c, so) { const uint32_t ko = (uint32_t)(c) * 128;               \
    _Pragma("unroll") for (int j = 0; j < 4; ++j)                              \
        CP16(dA + (so) + j * (32 * PITCH), hp + aoff[j] + ko);                 \
    _Pragma("unroll") for (int j = 0; j < 8; ++j)                              \
        CP16(dB + (so) + j * (32 * PITCH), wpb + (size_t)j * (32 * F_DIM * 2) + ko); \
    CP_COMMIT(); }

    LDM_SETUP();
    ACC_INIT();

    const int NC = F_DIM / 64;  // 64
    STAGE2(0, 0); STAGE2(1, STG_SZ);
    for (int c = 0; c < NC; ++c) {
        if (c + 1 < NC) { CP_WAIT(1); } else { CP_WAIT(0); }
        __syncthreads();
        if (c + 2 < NC) {
            const int cn = c + 2;
            STAGE2(cn, (uint32_t)(cn % 3) * STG_SZ);
        }
        CHUNK((uint32_t)(c % 3) * STG_SZ);
    }

    // epilogue: (acc + bias) * wt -> atomicAdd scatter (2 adds/elem onto 0)
    const int gid2 = lane >> 2, tg = lane & 3;
#pragma unroll
    for (int mt = 0; mt < 4; ++mt)
#pragma unroll
        for (int nt = 0; nt < 8; ++nt) {
            const int n = wn + nt * 8 + tg * 2;
            const float bv0 = bias_s[n], bv1 = bias_s[n + 1];
#pragma unroll
            for (int h = 0; h < 2; ++h) {
                const int m = wm + mt * 16 + gid2 + h * 8;
                if (m0 + m < cnt) {
                    const int   t = toks_s[m];
                    const float w = wts_s[m];
                    float* op = out + (size_t)t * D_DIM + n0 + n;
                    atomicAdd(op,     (acc[mt][nt][2 * h + 0] + bv0) * w);
                    atomicAdd(op + 1, (acc[mt][nt][2 * h + 1] + bv1) * w);
                }
            }
        }
}

// ---------------- launch -----------------------------------------------------
extern "C" void kernel_launch(void* const* d_in, const int* in_sizes, int n_in,
                              void* d_out, int out_size) {
    const float* x  = (const float*)d_in[0];
    const float* gw = (const float*)d_in[1];
    const float* w1 = (const float*)d_in[2];
    const float* b1 = (const float*)d_in[3];
    const float* w2 = (const float*)d_in[4];
    const float* b2 = (const float*)d_in[5];
    float* out   = (float*)d_out;
    float* probs = out + (size_t)T_TOK * D_DIM;

    cudaFuncSetAttribute(k_fc1_h, cudaFuncAttributeMaxDynamicSharedMemorySize, SMEM_DYN);
    cudaFuncSetAttribute(k_fc2_h, cudaFuncAttributeMaxDynamicSharedMemorySize, SMEM_DYN);

    k_init<<<512, 256>>>((float4*)out);
    k_split<<<1024, 256>>>(x, w1, w2);
    k_gate<<<T_TOK / 8, 256>>>(x, gw, probs);
    k_prefix<<<1, 32>>>();
    k_fc1_h<<<dim3(F_DIM / 256, T_TOK / 128, E_EXP), 256, SMEM_DYN>>>(b1);
    k_fc2_h<<<dim3(D_DIM / 256, T_TOK / 128, E_EXP), 256, SMEM_DYN>>>(b2, out);
}

// round 10
// speedup vs baseline: 1.1560x; 1.1560x over previous
#include <cuda_runtime.h>
#include <cuda_fp16.h>
#include <math.h>
#include <stdint.h>

#define T_TOK 8192
#define D_DIM 1024
#define F_DIM 4096
#define E_EXP 8

// ---------------- scratch (static device globals; no allocations) ----------
__device__ int    g_cnt[E_EXP];
__device__ int    g_off[E_EXP];
__device__ int    g_tok[E_EXP * T_TOK];
__device__ float  g_wt [E_EXP * T_TOK];

__device__ __half g_xh [(size_t)T_TOK * D_DIM];
__device__ __half g_w1h[(size_t)E_EXP * F_DIM * D_DIM];
__device__ __half g_w2h[(size_t)E_EXP * D_DIM * F_DIM];
__device__ __half g_hh [(size_t)2 * T_TOK * F_DIM];

// ---------------- PTX helpers (sm_80+ features only) ------------------------
__device__ __forceinline__ uint32_t smem_u32(const void* p) {
    uint32_t a;
    asm("{ .reg .u64 t; cvta.to.shared.u64 t, %1; cvt.u32.u64 %0, t; }" : "=r"(a) : "l"(p));
    return a;
}
#define CP16(dst, src) asm volatile("cp.async.cg.shared.global [%0], [%1], 16;" :: "r"(dst), "l"(src) : "memory")
#define CP_COMMIT()    asm volatile("cp.async.commit_group;" ::: "memory")
#define CP_WAIT(n)     asm volatile("cp.async.wait_group %0;" :: "n"(n) : "memory")
#define LDX4(r, a)                                                             \
    asm volatile("ldmatrix.sync.aligned.m8n8.x4.shared.b16 {%0,%1,%2,%3}, [%4];" \
        : "=r"((r)[0]), "=r"((r)[1]), "=r"((r)[2]), "=r"((r)[3]) : "r"(a))
#define MMAH(d, a, b0, b1)                                                     \
    asm volatile("mma.sync.aligned.m16n8k16.row.col.f32.f16.f16.f32 "          \
        "{%0,%1,%2,%3},{%4,%5,%6,%7},{%8,%9},{%0,%1,%2,%3};"                   \
        : "+f"((d)[0]), "+f"((d)[1]), "+f"((d)[2]), "+f"((d)[3])               \
        : "r"((a)[0]), "r"((a)[1]), "r"((a)[2]), "r"((a)[3]), "r"(b0), "r"(b1))

__device__ __forceinline__ uint32_t pack_h(__half a, __half b) {
    return ((uint32_t)__half_as_ushort(b) << 16) | __half_as_ushort(a);
}

// SMEM: toks @0 (512B), bias @512 (512B), wts @1024 (512B), stages @2048.
// Stage (k-chunk 64 fp16 = 128B, pitch 144B): A @0 (128x144), B @18432.
// 3-stage ring: 2048 + 3*36864 = 112640 B/CTA -> 2 CTAs/SM (225 KB < 228 KB).
#define SM_HDR  2048
#define PITCH   144
#define STG_SZ  36864
#define NSTAGE  3
#define SMEM_DYN (SM_HDR + NSTAGE * STG_SZ)

// ---------------- fused init + convert fp32 -> fp16 -------------------------
__global__ void k_split(const float* __restrict__ x, const float* __restrict__ w1,
                        const float* __restrict__ w2, float4* __restrict__ out4) {
    size_t stride = (size_t)gridDim.x * blockDim.x;
    size_t i0 = (size_t)blockIdx.x * blockDim.x + threadIdx.x;
    if (i0 < E_EXP) g_cnt[i0] = 0;
    const size_t no4 = (size_t)T_TOK * D_DIM / 4;
    float4 z = make_float4(0.f, 0.f, 0.f, 0.f);
    for (size_t i = i0; i < no4; i += stride) out4[i] = z;
    const size_t nx4 = (size_t)T_TOK * D_DIM / 4;
    const size_t nw4 = (size_t)E_EXP * F_DIM * D_DIM / 4;
    uint2* xo  = (uint2*)g_xh;
    uint2* w1o = (uint2*)g_w1h;
    uint2* w2o = (uint2*)g_w2h;
    for (size_t i = i0; i < nx4; i += stride) {
        float4 f = ((const float4*)x)[i];
        xo[i] = make_uint2(pack_h(__float2half_rn(f.x), __float2half_rn(f.y)),
                           pack_h(__float2half_rn(f.z), __float2half_rn(f.w)));
    }
    for (size_t i = i0; i < nw4; i += stride) {
        float4 f = ((const float4*)w1)[i];
        w1o[i] = make_uint2(pack_h(__float2half_rn(f.x), __float2half_rn(f.y)),
                            pack_h(__float2half_rn(f.z), __float2half_rn(f.w)));
    }
    for (size_t i = i0; i < nw4; i += stride) {
        float4 f = ((const float4*)w2)[i];
        w2o[i] = make_uint2(pack_h(__float2half_rn(f.x), __float2half_rn(f.y)),
                            pack_h(__float2half_rn(f.z), __float2half_rn(f.w)));
    }
}

// ---------------- gating (validated) ----------------------------------------
__global__ void k_gate(const float* __restrict__ x, const float* __restrict__ gw,
                       float* __restrict__ probs_out) {
    int warp = (blockIdx.x * blockDim.x + threadIdx.x) >> 5;
    int lane = threadIdx.x & 31;
    if (warp >= T_TOK) return;
    const float* xr = x + (size_t)warp * D_DIM;
    float acc[E_EXP];
#pragma unroll
    for (int e = 0; e < E_EXP; e++) acc[e] = 0.f;
    for (int k = lane * 4; k < D_DIM; k += 128) {
        float4 xv = *(const float4*)(xr + k);
#pragma unroll
        for (int e = 0; e < E_EXP; e++) {
            float4 wv = *(const float4*)(gw + (size_t)e * D_DIM + k);
            acc[e] += xv.x * wv.x + xv.y * wv.y + xv.z * wv.z + xv.w * wv.w;
        }
    }
#pragma unroll
    for (int e = 0; e < E_EXP; e++)
#pragma unroll
        for (int o = 16; o > 0; o >>= 1) acc[e] += __shfl_xor_sync(0xffffffffu, acc[e], o);
    if (lane == 0) {
        float mx = acc[0];
#pragma unroll
        for (int e = 1; e < E_EXP; e++) mx = fmaxf(mx, acc[e]);
        float p[E_EXP], s = 0.f;
#pragma unroll
        for (int e = 0; e < E_EXP; e++) { p[e] = expf(acc[e] - mx); s += p[e]; }
        float inv = 1.f / s;
#pragma unroll
        for (int e = 0; e < E_EXP; e++) {
            p[e] *= inv;
            probs_out[(size_t)warp * E_EXP + e] = p[e];
        }
        int i0 = 0;
#pragma unroll
        for (int e = 1; e < E_EXP; e++) if (p[e] > p[i0]) i0 = e;
        int i1 = (i0 == 0) ? 1 : 0;
#pragma unroll
        for (int e = 0; e < E_EXP; e++) if (e != i0 && p[e] > p[i1]) i1 = e;
        float denom = p[i0] + p[i1] + 1e-9f;
        int s0 = atomicAdd(&g_cnt[i0], 1);
        g_tok[i0 * T_TOK + s0] = warp; g_wt[i0 * T_TOK + s0] = p[i0] / denom;
        int s1 = atomicAdd(&g_cnt[i1], 1);
        g_tok[i1 * T_TOK + s1] = warp; g_wt[i1 * T_TOK + s1] = p[i1] / denom;
    }
}
__global__ void k_prefix() {
    if (threadIdx.x == 0) {
        int run = 0;
#pragma unroll
        for (int e = 0; e < E_EXP; e++) { g_off[e] = run; run += g_cnt[e]; }
    }
}

// ---------------- GEMM core: block 128x128xk64, 8 warps, warp 32x64 ---------
#define LDM_SETUP()                                                            \
    const int lane = tid & 31, wid = tid >> 5;                                 \
    const int wm = (wid & 3) * 32, wn = (wid >> 2) * 64;                       \
    uint32_t aav[2];                                                           \
    _Pragma("unroll") for (int mt = 0; mt < 2; ++mt)                           \
        aav[mt] = sb + SM_HDR + (wm + mt * 16 + (lane & 15)) * PITCH +         \
                  ((lane >> 4) & 1) * 16;                                      \
    uint32_t bbv[4];                                                           \
    _Pragma("unroll") for (int g = 0; g < 4; ++g)                              \
        bbv[g] = sb + SM_HDR + 18432 +                                         \
            (wn + g * 16 + (lane & 7) + ((lane >> 4) & 1) * 8) * PITCH +       \
            ((lane >> 3) & 1) * 16;

// Fragment-pipelined chunk (validated R8): bit-identical per-accumulator order.
#define CHUNK(so) {                                                            \
    uint32_t Ah[2][2][4], Bh[2][4];                                            \
    LDX4(Ah[0][0], aav[0] + (so));                                             \
    LDX4(Ah[0][1], aav[1] + (so));                                             \
    LDX4(Bh[0], bbv[0] + (so));                                                \
    _Pragma("unroll") for (int kk = 0; kk < 4; ++kk) {                         \
        _Pragma("unroll") for (int g = 0; g < 4; ++g) {                        \
            const int cur = g & 1, nxt = cur ^ 1;                              \
            if (g < 3)       { LDX4(Bh[nxt], bbv[g + 1] + (so) + kk * 32); }   \
            else if (kk < 3) { LDX4(Bh[nxt], bbv[0] + (so) + (kk + 1) * 32); } \
            if (g == 0 && kk < 3) {                                            \
                LDX4(Ah[(kk + 1) & 1][0], aav[0] + (so) + (kk + 1) * 32);      \
                LDX4(Ah[(kk + 1) & 1][1], aav[1] + (so) + (kk + 1) * 32);      \
            }                                                                  \
            MMAH(acc[0][2 * g],     Ah[kk & 1][0], Bh[cur][0], Bh[cur][1]);    \
            MMAH(acc[1][2 * g],     Ah[kk & 1][1], Bh[cur][0], Bh[cur][1]);    \
            MMAH(acc[0][2 * g + 1], Ah[kk & 1][0], Bh[cur][2], Bh[cur][3]);    \
            MMAH(acc[1][2 * g + 1], Ah[kk & 1][1], Bh[cur][2], Bh[cur][3]);    \
        }                                                                      \
    }                                                                          \
}

#define ACC_INIT()                                                             \
    float acc[2][8][4];                                                        \
    _Pragma("unroll") for (int i = 0; i < 2; i++)                              \
        _Pragma("unroll") for (int j = 0; j < 8; j++)                          \
            _Pragma("unroll") for (int k = 0; k < 4; k++) acc[i][j][k] = 0.f;

// ---------------- fc1: h = gelu(X[gather] @ W1e^T + b1) -> fp16 -------------
__global__ __launch_bounds__(256, 2) void k_fc1_h(const float* __restrict__ b1) {
    const int e = blockIdx.z;
    const int cnt = g_cnt[e];
    const int m0 = blockIdx.y * 128;
    if (m0 >= cnt) return;
    const int n0 = blockIdx.x * 128;

    extern __shared__ __align__(128) char smp[];
    const uint32_t sb = smem_u32(smp);
    int*   toks_s = (int*)smp;
    float* bias_s = (float*)(smp + 512);
    const int tid = threadIdx.x;
    if (tid < 128) {
        toks_s[tid] = g_tok[e * T_TOK + min(m0 + tid, cnt - 1)];
        bias_s[tid] = b1[e * F_DIM + n0 + tid];
    }
    __syncthreads();

    // staging: q = tid&7 (16B quad of 128B row), r = tid>>3 (0..31), rows r+32j
    const int q = tid & 7, r = tid >> 3;
    const uint32_t dA = sb + SM_HDR + r * PITCH + q * 16;
    const uint32_t dB = dA + 18432;
    const char* xp = (const char*)g_xh;
    size_t aoff[4];
    const char* wp[4];
#pragma unroll
    for (int j = 0; j < 4; ++j) {
        aoff[j] = (size_t)toks_s[r + 32 * j] * (D_DIM * 2) + q * 16;
        wp[j] = (const char*)(g_w1h + ((size_t)e * F_DIM + n0 + r + 32 * j) * D_DIM) + q * 16;
    }

#define STAGE1(c, so) { const uint32_t ko = (uint32_t)(c) * 128;               \
    _Pragma("unroll") for (int j = 0; j < 4; ++j) {                            \
        CP16(dA + (so) + j * (32 * PITCH), xp + aoff[j] + ko);                 \
        CP16(dB + (so) + j * (32 * PITCH), wp[j] + ko);                        \
    }                                                                          \
    CP_COMMIT(); }

    LDM_SETUP();
    ACC_INIT();

    const int NC = D_DIM / 64;  // 16
    STAGE1(0, 0); STAGE1(1, STG_SZ);
    for (int c = 0; c < NC; ++c) {
        if (c + 1 < NC) { CP_WAIT(1); } else { CP_WAIT(0); }
        __syncthreads();
        if (c + 2 < NC) {
            const int cn = c + 2;
            STAGE1(cn, (uint32_t)(cn % 3) * STG_SZ);
        }
        CHUNK((uint32_t)(c % 3) * STG_SZ);
    }

    // epilogue: bias + exact gelu -> fp16 -> g_hh
    const int gid2 = lane >> 2, tg = lane & 3;
    const int hbase = g_off[e] + m0;
    uint32_t* gh = (uint32_t*)g_hh;
#pragma unroll
    for (int mt = 0; mt < 2; ++mt)
#pragma unroll
        for (int nt = 0; nt < 8; ++nt) {
            const int n = wn + nt * 8 + tg * 2;
            const float bv0 = bias_s[n], bv1 = bias_s[n + 1];
#pragma unroll
            for (int h = 0; h < 2; ++h) {
                const int m = wm + mt * 16 + gid2 + h * 8;
                if (m0 + m < cnt) {
                    float v0 = acc[mt][nt][2 * h + 0] + bv0;
                    float v1 = acc[mt][nt][2 * h + 1] + bv1;
                    v0 = 0.5f * v0 * (1.f + erff(v0 * 0.7071067811865476f));
                    v1 = 0.5f * v1 * (1.f + erff(v1 * 0.7071067811865476f));
                    gh[(size_t)(hbase + m) * (F_DIM / 2) + (size_t)(n0 + n) / 2] =
                        pack_h(__float2half_rn(v0), __float2half_rn(v1));
                }
            }
        }
}

// ---------------- fc2: out[tok] += w * (H @ W2e^T + b2) ---------------------
__global__ __launch_bounds__(256, 2) void k_fc2_h(const float* __restrict__ b2,
                                                  float* __restrict__ out) {
    const int e = blockIdx.z;
    const int cnt = g_cnt[e];
    const int m0 = blockIdx.y * 128;
    if (m0 >= cnt) return;
    const int n0 = blockIdx.x * 128;

    extern __shared__ __align__(128) char smp[];
    const uint32_t sb = smem_u32(smp);
    int*   toks_s = (int*)smp;
    float* bias_s = (float*)(smp + 512);
    float* wts_s  = (float*)(smp + 1024);
    const int tid = threadIdx.x;
    if (tid < 128) {
        const int sl = min(m0 + tid, cnt - 1);
        toks_s[tid] = g_tok[e * T_TOK + sl];
        wts_s[tid]  = g_wt [e * T_TOK + sl];
        bias_s[tid] = b2[e * D_DIM + n0 + tid];
    }
    __syncthreads();

    const int q = tid & 7, r = tid >> 3;
    const uint32_t dA = sb + SM_HDR + r * PITCH + q * 16;
    const uint32_t dB = dA + 18432;
    const char* hp = (const char*)g_hh;
    size_t aoff[4];
    const char* wp[4];
#pragma unroll
    for (int j = 0; j < 4; ++j) {
        aoff[j] = (size_t)(g_off[e] + min(m0 + r + 32 * j, cnt - 1)) * (F_DIM * 2) + q * 16;
        wp[j] = (const char*)(g_w2h + ((size_t)e * D_DIM + n0 + r + 32 * j) * F_DIM) + q * 16;
    }

#define STAGE2(c, so) { const uint32_t ko = (uint32_t)(c) * 128;               \
    _Pragma("unroll") for (int j = 0; j < 4; ++j) {                            \
        CP16(dA + (so) + j * (32 * PITCH), hp + aoff[j] + ko);                 \
        CP16(dB + (so) + j * (32 * PITCH), wp[j] + ko);                        \
    }                                                                          \
    CP_COMMIT(); }

    LDM_SETUP();
    ACC_INIT();

    const int NC = F_DIM / 64;  // 64
    STAGE2(0, 0); STAGE2(1, STG_SZ);
    for (int c = 0; c < NC; ++c) {
        if (c + 1 < NC) { CP_WAIT(1); } else { CP_WAIT(0); }
        __syncthreads();
        if (c + 2 < NC) {
            const int cn = c + 2;
            STAGE2(cn, (uint32_t)(cn % 3) * STG_SZ);
        }
        CHUNK((uint32_t)(c % 3) * STG_SZ);
    }

    // epilogue: (acc + bias) * wt -> atomicAdd scatter (2 adds/elem onto 0)
    const int gid2 = lane >> 2, tg = lane & 3;
#pragma unroll
    for (int mt = 0; mt < 2; ++mt)
#pragma unroll
        for (int nt = 0; nt < 8; ++nt) {
            const int n = wn + nt * 8 + tg * 2;
            const float bv0 = bias_s[n], bv1 = bias_s[n + 1];
#pragma unroll
            for (int h = 0; h < 2; ++h) {
                const int m = wm + mt * 16 + gid2 + h * 8;
                if (m0 + m < cnt) {
                    const int   t = toks_s[m];
                    const float w = wts_s[m];
                    float* op = out + (size_t)t * D_DIM + n0 + n;
                    atomicAdd(op,     (acc[mt][nt][2 * h + 0] + bv0) * w);
                    atomicAdd(op + 1, (acc[mt][nt][2 * h + 1] + bv1) * w);
                }
            }
        }
}

// ---------------- launch -----------------------------------------------------
extern "C" void kernel_launch(void* const* d_in, const int* in_sizes, int n_in,
                              void* d_out, int out_size) {
    const float* x  = (const float*)d_in[0];
    const float* gw = (const float*)d_in[1];
    const float* w1 = (const float*)d_in[2];
    const float* b1 = (const float*)d_in[3];
    const float* w2 = (const float*)d_in[4];
    const float* b2 = (const float*)d_in[5];
    float* out   = (float*)d_out;
    float* probs = out + (size_t)T_TOK * D_DIM;

    cudaFuncSetAttribute(k_fc1_h, cudaFuncAttributeMaxDynamicSharedMemorySize, SMEM_DYN);
    cudaFuncSetAttribute(k_fc2_h, cudaFuncAttributeMaxDynamicSharedMemorySize, SMEM_DYN);

    k_split<<<1024, 256>>>(x, w1, w2, (float4*)out);
    k_gate<<<T_TOK / 8, 256>>>(x, gw, probs);
    k_prefix<<<1, 32>>>();
    k_fc1_h<<<dim3(F_DIM / 128, T_TOK / 128, E_EXP), 256, SMEM_DYN>>>(b1);
    k_fc2_h<<<dim3(D_DIM / 128, T_TOK / 128, E_EXP), 256, SMEM_DYN>>>(b2, out);
}

// round 11
// speedup vs baseline: 1.1759x; 1.0172x over previous
#include <cuda_runtime.h>
#include <cuda_fp16.h>
#include <math.h>
#include <stdint.h>

#define T_TOK 8192
#define D_DIM 1024
#define F_DIM 4096
#define E_EXP 8

// ---------------- scratch (static device globals; no allocations) ----------
__device__ int    g_cnt[E_EXP];
__device__ int    g_tok[E_EXP * T_TOK];
__device__ float  g_wt [E_EXP * T_TOK];

__device__ __half g_xh [(size_t)T_TOK * D_DIM];
__device__ __half g_w1h[(size_t)E_EXP * F_DIM * D_DIM];
__device__ __half g_w2h[(size_t)E_EXP * D_DIM * F_DIM];
__device__ __half g_hh [(size_t)2 * T_TOK * F_DIM];

// ---------------- PTX helpers (sm_80+ features only) ------------------------
__device__ __forceinline__ uint32_t smem_u32(const void* p) {
    uint32_t a;
    asm("{ .reg .u64 t; cvta.to.shared.u64 t, %1; cvt.u32.u64 %0, t; }" : "=r"(a) : "l"(p));
    return a;
}
#define CP16(dst, src) asm volatile("cp.async.cg.shared.global [%0], [%1], 16;" :: "r"(dst), "l"(src) : "memory")
#define CP_COMMIT()    asm volatile("cp.async.commit_group;" ::: "memory")
#define CP_WAIT(n)     asm volatile("cp.async.wait_group %0;" :: "n"(n) : "memory")
#define LDX4(r, a)                                                             \
    asm volatile("ldmatrix.sync.aligned.m8n8.x4.shared.b16 {%0,%1,%2,%3}, [%4];" \
        : "=r"((r)[0]), "=r"((r)[1]), "=r"((r)[2]), "=r"((r)[3]) : "r"(a))
#define MMAH(d, a, b0, b1)                                                     \
    asm volatile("mma.sync.aligned.m16n8k16.row.col.f32.f16.f16.f32 "          \
        "{%0,%1,%2,%3},{%4,%5,%6,%7},{%8,%9},{%0,%1,%2,%3};"                   \
        : "+f"((d)[0]), "+f"((d)[1]), "+f"((d)[2]), "+f"((d)[3])               \
        : "r"((a)[0]), "r"((a)[1]), "r"((a)[2]), "r"((a)[3]), "r"(b0), "r"(b1))

__device__ __forceinline__ uint32_t pack_h(__half a, __half b) {
    return ((uint32_t)__half_as_ushort(b) << 16) | __half_as_ushort(a);
}

// SMEM: toks @0 (512B), bias @512 (512B), wts @1024 (512B), stages @2048.
// Stage (k-chunk 64 fp16 = 128B, pitch 144B): A @0 (128x144), B @18432.
// 3-stage ring: 2048 + 3*36864 = 112640 B/CTA -> 2 CTAs/SM.
#define SM_HDR  2048
#define PITCH   144
#define STG_SZ  36864
#define SMEM_DYN (SM_HDR + 3 * STG_SZ)

// ---------------- fused init + convert fp32 -> fp16 -------------------------
__global__ void k_split(const float* __restrict__ x, const float* __restrict__ w1,
                        const float* __restrict__ w2, float4* __restrict__ out4) {
    size_t stride = (size_t)gridDim.x * blockDim.x;
    size_t i0 = (size_t)blockIdx.x * blockDim.x + threadIdx.x;
    if (i0 < E_EXP) g_cnt[i0] = 0;
    const size_t no4 = (size_t)T_TOK * D_DIM / 4;
    float4 z = make_float4(0.f, 0.f, 0.f, 0.f);
    for (size_t i = i0; i < no4; i += stride) out4[i] = z;
    const size_t nx4 = (size_t)T_TOK * D_DIM / 4;
    const size_t nw4 = (size_t)E_EXP * F_DIM * D_DIM / 4;
    uint2* xo  = (uint2*)g_xh;
    uint2* w1o = (uint2*)g_w1h;
    uint2* w2o = (uint2*)g_w2h;
    for (size_t i = i0; i < nx4; i += stride) {
        float4 f = ((const float4*)x)[i];
        xo[i] = make_uint2(pack_h(__float2half_rn(f.x), __float2half_rn(f.y)),
                           pack_h(__float2half_rn(f.z), __float2half_rn(f.w)));
    }
    for (size_t i = i0; i < nw4; i += stride) {
        float4 f = ((const float4*)w1)[i];
        w1o[i] = make_uint2(pack_h(__float2half_rn(f.x), __float2half_rn(f.y)),
                            pack_h(__float2half_rn(f.z), __float2half_rn(f.w)));
    }
    for (size_t i = i0; i < nw4; i += stride) {
        float4 f = ((const float4*)w2)[i];
        w2o[i] = make_uint2(pack_h(__float2half_rn(f.x), __float2half_rn(f.y)),
                            pack_h(__float2half_rn(f.z), __float2half_rn(f.w)));
    }
}

// ---------------- gating (validated) ----------------------------------------
__global__ void k_gate(const float* __restrict__ x, const float* __restrict__ gw,
                       float* __restrict__ probs_out) {
    int warp = (blockIdx.x * blockDim.x + threadIdx.x) >> 5;
    int lane = threadIdx.x & 31;
    if (warp >= T_TOK) return;
    const float* xr = x + (size_t)warp * D_DIM;
    float acc[E_EXP];
#pragma unroll
    for (int e = 0; e < E_EXP; e++) acc[e] = 0.f;
    for (int k = lane * 4; k < D_DIM; k += 128) {
        float4 xv = *(const float4*)(xr + k);
#pragma unroll
        for (int e = 0; e < E_EXP; e++) {
            float4 wv = *(const float4*)(gw + (size_t)e * D_DIM + k);
            acc[e] += xv.x * wv.x + xv.y * wv.y + xv.z * wv.z + xv.w * wv.w;
        }
    }
#pragma unroll
    for (int e = 0; e < E_EXP; e++)
#pragma unroll
        for (int o = 16; o > 0; o >>= 1) acc[e] += __shfl_xor_sync(0xffffffffu, acc[e], o);
    if (lane == 0) {
        float mx = acc[0];
#pragma unroll
        for (int e = 1; e < E_EXP; e++) mx = fmaxf(mx, acc[e]);
        float p[E_EXP], s = 0.f;
#pragma unroll
        for (int e = 0; e < E_EXP; e++) { p[e] = expf(acc[e] - mx); s += p[e]; }
        float inv = 1.f / s;
#pragma unroll
        for (int e = 0; e < E_EXP; e++) {
            p[e] *= inv;
            probs_out[(size_t)warp * E_EXP + e] = p[e];
        }
        int i0 = 0;
#pragma unroll
        for (int e = 1; e < E_EXP; e++) if (p[e] > p[i0]) i0 = e;
        int i1 = (i0 == 0) ? 1 : 0;
#pragma unroll
        for (int e = 0; e < E_EXP; e++) if (e != i0 && p[e] > p[i1]) i1 = e;
        float denom = p[i0] + p[i1] + 1e-9f;
        int s0 = atomicAdd(&g_cnt[i0], 1);
        g_tok[i0 * T_TOK + s0] = warp; g_wt[i0 * T_TOK + s0] = p[i0] / denom;
        int s1 = atomicAdd(&g_cnt[i1], 1);
        g_tok[i1 * T_TOK + s1] = warp; g_wt[i1 * T_TOK + s1] = p[i1] / denom;
    }
}

// ---------------- inline prefix over 8 counters ------------------------------
__device__ __forceinline__ int expert_off(int e) {
    int off = 0;
#pragma unroll
    for (int i = 0; i < E_EXP - 1; ++i)
        if (i < e) off += g_cnt[i];
    return off;
}

// ---------------- GEMM core: block 128x128xk64, 8 warps, warp 32x64 ---------
#define LDM_SETUP()                                                            \
    const int lane = tid & 31, wid = tid >> 5;                                 \
    const int wm = (wid & 3) * 32, wn = (wid >> 2) * 64;                       \
    uint32_t aav[2];                                                           \
    _Pragma("unroll") for (int mt = 0; mt < 2; ++mt)                           \
        aav[mt] = sb + SM_HDR + (wm + mt * 16 + (lane & 15)) * PITCH +         \
                  ((lane >> 4) & 1) * 16;                                      \
    uint32_t bbv[4];                                                           \
    _Pragma("unroll") for (int g = 0; g < 4; ++g)                              \
        bbv[g] = sb + SM_HDR + 18432 +                                         \
            (wn + g * 16 + (lane & 7) + ((lane >> 4) & 1) * 8) * PITCH +       \
            ((lane >> 3) & 1) * 16;

// Fragment-pipelined chunk (validated R8): bit-identical per-accumulator order.
// 'so' is a compile-time constant at every expansion (ring-period unrolling),
// so all ldmatrix/cp.async smem addresses fold to reg+immediate.
#define CHUNK(so) {                                                            \
    uint32_t Ah[2][2][4], Bh[2][4];                                            \
    LDX4(Ah[0][0], aav[0] + (so));                                             \
    LDX4(Ah[0][1], aav[1] + (so));                                             \
    LDX4(Bh[0], bbv[0] + (so));                                                \
    _Pragma("unroll") for (int kk = 0; kk < 4; ++kk) {                         \
        _Pragma("unroll") for (int g = 0; g < 4; ++g) {                        \
            const int cur = g & 1, nxt = cur ^ 1;                              \
            if (g < 3)       { LDX4(Bh[nxt], bbv[g + 1] + (so) + kk * 32); }   \
            else if (kk < 3) { LDX4(Bh[nxt], bbv[0] + (so) + (kk + 1) * 32); } \
            if (g == 0 && kk < 3) {                                            \
                LDX4(Ah[(kk + 1) & 1][0], aav[0] + (so) + (kk + 1) * 32);      \
                LDX4(Ah[(kk + 1) & 1][1], aav[1] + (so) + (kk + 1) * 32);      \
            }                                                                  \
            MMAH(acc[0][2 * g],     Ah[kk & 1][0], Bh[cur][0], Bh[cur][1]);    \
            MMAH(acc[1][2 * g],     Ah[kk & 1][1], Bh[cur][0], Bh[cur][1]);    \
            MMAH(acc[0][2 * g + 1], Ah[kk & 1][0], Bh[cur][2], Bh[cur][3]);    \
            MMAH(acc[1][2 * g + 1], Ah[kk & 1][1], Bh[cur][2], Bh[cur][3]);    \
        }                                                                      \
    }                                                                          \
}

#define ACC_INIT()                                                             \
    float acc[2][8][4];                                                        \
    _Pragma("unroll") for (int i = 0; i < 2; i++)                              \
        _Pragma("unroll") for (int j = 0; j < 8; j++)                          \
            _Pragma("unroll") for (int k = 0; k < 4; k++) acc[i][j][k] = 0.f;

// ---------------- fc1: h = gelu(X[gather] @ W1e^T + b1) -> fp16 -------------
__global__ __launch_bounds__(256, 2) void k_fc1_h(const float* __restrict__ b1) {
    const int e = blockIdx.z;
    const int cnt = g_cnt[e];
    const int m0 = blockIdx.y * 128;
    if (m0 >= cnt) return;
    const int n0 = blockIdx.x * 128;

    extern __shared__ __align__(128) char smp[];
    const uint32_t sb = smem_u32(smp);
    int*   toks_s = (int*)smp;
    float* bias_s = (float*)(smp + 512);
    const int tid = threadIdx.x;
    if (tid < 128) {
        toks_s[tid] = g_tok[e * T_TOK + min(m0 + tid, cnt - 1)];
        bias_s[tid] = b1[e * F_DIM + n0 + tid];
    }
    __syncthreads();

    // staging: q = tid&7 (16B quad of 128B row), r = tid>>3 (0..31), rows r+32j
    const int q = tid & 7, r = tid >> 3;
    const uint32_t dA = sb + SM_HDR + r * PITCH + q * 16;
    const uint32_t dB = dA + 18432;
    const char* xp = (const char*)g_xh;
    size_t aoff[4];
    const char* wp[4];
#pragma unroll
    for (int j = 0; j < 4; ++j) {
        aoff[j] = (size_t)toks_s[r + 32 * j] * (D_DIM * 2) + q * 16;
        wp[j] = (const char*)(g_w1h + ((size_t)e * F_DIM + n0 + r + 32 * j) * D_DIM) + q * 16;
    }

#define STAGE1(c, so) { const uint32_t ko = (uint32_t)(c) * 128;               \
    _Pragma("unroll") for (int j = 0; j < 4; ++j) {                            \
        CP16(dA + (so) + j * (32 * PITCH), xp + aoff[j] + ko);                 \
        CP16(dB + (so) + j * (32 * PITCH), wp[j] + ko);                        \
    }                                                                          \
    CP_COMMIT(); }

    LDM_SETUP();
    ACC_INIT();

    const int NC = D_DIM / 64;  // 16
    STAGE1(0, 0); STAGE1(1, STG_SZ);
#define ITER1(cc, SO)                                                          \
    if ((cc) < NC) {                                                           \
        if ((cc) + 1 < NC) { CP_WAIT(1); } else { CP_WAIT(0); }                \
        __syncthreads();                                                       \
        if ((cc) + 2 < NC) STAGE1((cc) + 2, ((SO) + 2 * STG_SZ) % (3 * STG_SZ)); \
        CHUNK(SO);                                                             \
    }
    for (int cb = 0; cb < NC; cb += 3) {
        ITER1(cb, 0);
        ITER1(cb + 1, STG_SZ);
        ITER1(cb + 2, 2 * STG_SZ);
    }

    // epilogue: bias + exact gelu -> fp16 -> g_hh
    const int gid2 = lane >> 2, tg = lane & 3;
    const int hbase = expert_off(e) + m0;
    uint32_t* gh = (uint32_t*)g_hh;
#pragma unroll
    for (int mt = 0; mt < 2; ++mt)
#pragma unroll
        for (int nt = 0; nt < 8; ++nt) {
            const int n = wn + nt * 8 + tg * 2;
            const float bv0 = bias_s[n], bv1 = bias_s[n + 1];
#pragma unroll
            for (int h = 0; h < 2; ++h) {
                const int m = wm + mt * 16 + gid2 + h * 8;
                if (m0 + m < cnt) {
                    float v0 = acc[mt][nt][2 * h + 0] + bv0;
                    float v1 = acc[mt][nt][2 * h + 1] + bv1;
                    v0 = 0.5f * v0 * (1.f + erff(v0 * 0.7071067811865476f));
                    v1 = 0.5f * v1 * (1.f + erff(v1 * 0.7071067811865476f));
                    gh[(size_t)(hbase + m) * (F_DIM / 2) + (size_t)(n0 + n) / 2] =
                        pack_h(__float2half_rn(v0), __float2half_rn(v1));
                }
            }
        }
}

// ---------------- fc2: out[tok] += w * (H @ W2e^T + b2) ---------------------
__global__ __launch_bounds__(256, 2) void k_fc2_h(const float* __restrict__ b2,
                                                  float* __restrict__ out) {
    const int e = blockIdx.z;
    const int cnt = g_cnt[e];
    const int m0 = blockIdx.y * 128;
    if (m0 >= cnt) return;
    const int n0 = blockIdx.x * 128;

    extern __shared__ __align__(128) char smp[];
    const uint32_t sb = smem_u32(smp);
    int*   toks_s = (int*)smp;
    float* bias_s = (float*)(smp + 512);
    float* wts_s  = (float*)(smp + 1024);
    const int tid = threadIdx.x;
    if (tid < 128) {
        const int sl = min(m0 + tid, cnt - 1);
        toks_s[tid] = g_tok[e * T_TOK + sl];
        wts_s[tid]  = g_wt [e * T_TOK + sl];
        bias_s[tid] = b2[e * D_DIM + n0 + tid];
    }
    __syncthreads();

    const int q = tid & 7, r = tid >> 3;
    const uint32_t dA = sb + SM_HDR + r * PITCH + q * 16;
    const uint32_t dB = dA + 18432;
    const char* hp = (const char*)g_hh;
    const int off = expert_off(e);
    size_t aoff[4];
    const char* wp[4];
#pragma unroll
    for (int j = 0; j < 4; ++j) {
        aoff[j] = (size_t)(off + min(m0 + r + 32 * j, cnt - 1)) * (F_DIM * 2) + q * 16;
        wp[j] = (const char*)(g_w2h + ((size_t)e * D_DIM + n0 + r + 32 * j) * F_DIM) + q * 16;
    }

#define STAGE2(c, so) { const uint32_t ko = (uint32_t)(c) * 128;               \
    _Pragma("unroll") for (int j = 0; j < 4; ++j) {                            \
        CP16(dA + (so) + j * (32 * PITCH), hp + aoff[j] + ko);                 \
        CP16(dB + (so) + j * (32 * PITCH), wp[j] + ko);                        \
    }                                                                          \
    CP_COMMIT(); }

    LDM_SETUP();
    ACC_INIT();

    const int NC = F_DIM / 64;  // 64
    STAGE2(0, 0); STAGE2(1, STG_SZ);
#define ITER2(cc, SO)                                                          \
    if ((cc) < NC) {                                                           \
        if ((cc) + 1 < NC) { CP_WAIT(1); } else { CP_WAIT(0); }                \
        __syncthreads();                                                       \
        if ((cc) + 2 < NC) STAGE2((cc) + 2, ((SO) + 2 * STG_SZ) % (3 * STG_SZ)); \
        CHUNK(SO);                                                             \
    }
    for (int cb = 0; cb < NC; cb += 3) {
        ITER2(cb, 0);
        ITER2(cb + 1, STG_SZ);
        ITER2(cb + 2, 2 * STG_SZ);
    }

    // epilogue: (acc + bias) * wt -> atomicAdd scatter (2 adds/elem onto 0)
    const int gid2 = lane >> 2, tg = lane & 3;
#pragma unroll
    for (int mt = 0; mt < 2; ++mt)
#pragma unroll
        for (int nt = 0; nt < 8; ++nt) {
            const int n = wn + nt * 8 + tg * 2;
            const float bv0 = bias_s[n], bv1 = bias_s[n + 1];
#pragma unroll
            for (int h = 0; h < 2; ++h) {
                const int m = wm + mt * 16 + gid2 + h * 8;
                if (m0 + m < cnt) {
                    const int   t = toks_s[m];
                    const float w = wts_s[m];
                    float* op = out + (size_t)t * D_DIM + n0 + n;
                    atomicAdd(op,     (acc[mt][nt][2 * h + 0] + bv0) * w);
                    atomicAdd(op + 1, (acc[mt][nt][2 * h + 1] + bv1) * w);
                }
            }
        }
}

// ---------------- launch -----------------------------------------------------
extern "C" void kernel_launch(void* const* d_in, const int* in_sizes, int n_in,
                              void* d_out, int out_size) {
    const float* x  = (const float*)d_in[0];
    const float* gw = (const float*)d_in[1];
    const float* w1 = (const float*)d_in[2];
    const float* b1 = (const float*)d_in[3];
    const float* w2 = (const float*)d_in[4];
    const float* b2 = (const float*)d_in[5];
    float* out   = (float*)d_out;
    float* probs = out + (size_t)T_TOK * D_DIM;

    cudaFuncSetAttribute(k_fc1_h, cudaFuncAttributeMaxDynamicSharedMemorySize, SMEM_DYN);
    cudaFuncSetAttribute(k_fc2_h, cudaFuncAttributeMaxDynamicSharedMemorySize, SMEM_DYN);

    k_split<<<1024, 256>>>(x, w1, w2, (float4*)out);
    k_gate<<<T_TOK / 8, 256>>>(x, gw, probs);
    k_fc1_h<<<dim3(F_DIM / 128, T_TOK / 128, E_EXP), 256, SMEM_DYN>>>(b1);
    k_fc2_h<<<dim3(D_DIM / 128, T_TOK / 128, E_EXP), 256, SMEM_DYN>>>(b2, out);
}

// round 12
// speedup vs baseline: 1.3017x; 1.1070x over previous
#include <cuda_runtime.h>
#include <cuda_fp16.h>
#include <math.h>
#include <stdint.h>

#define T_TOK 8192
#define D_DIM 1024
#define F_DIM 4096
#define E_EXP 8

// ---------------- scratch (static device globals; no allocations) ----------
__device__ int    g_cnt[E_EXP];
__device__ int    g_tok[E_EXP * T_TOK];
__device__ float  g_wt [E_EXP * T_TOK];

__device__ __half g_xh [(size_t)T_TOK * D_DIM];
__device__ __half g_w1h[(size_t)E_EXP * F_DIM * D_DIM];
__device__ __half g_w2h[(size_t)E_EXP * D_DIM * F_DIM];
__device__ __half g_hh [(size_t)2 * T_TOK * F_DIM];

// ---------------- PTX helpers (sm_80+ features only) ------------------------
__device__ __forceinline__ uint32_t smem_u32(const void* p) {
    uint32_t a;
    asm("{ .reg .u64 t; cvta.to.shared.u64 t, %1; cvt.u32.u64 %0, t; }" : "=r"(a) : "l"(p));
    return a;
}
#define CP16(dst, src) asm volatile("cp.async.cg.shared.global [%0], [%1], 16;" :: "r"(dst), "l"(src) : "memory")
#define LDX4(r, a)                                                             \
    asm volatile("ldmatrix.sync.aligned.m8n8.x4.shared.b16 {%0,%1,%2,%3}, [%4];" \
        : "=r"((r)[0]), "=r"((r)[1]), "=r"((r)[2]), "=r"((r)[3]) : "r"(a))
#define MMAH(d, a, b0, b1)                                                     \
    asm volatile("mma.sync.aligned.m16n8k16.row.col.f32.f16.f16.f32 "          \
        "{%0,%1,%2,%3},{%4,%5,%6,%7},{%8,%9},{%0,%1,%2,%3};"                   \
        : "+f"((d)[0]), "+f"((d)[1]), "+f"((d)[2]), "+f"((d)[3])               \
        : "r"((a)[0]), "r"((a)[1]), "r"((a)[2]), "r"((a)[3]), "r"(b0), "r"(b1))

// mbarrier flow control (sm_80 mbarrier + cp.async integration)
#define MB_INIT(mb, c)  asm volatile("mbarrier.init.shared.b64 [%0], %1;" :: "r"(mb), "r"(c) : "memory")
#define MB_ARRIVE(mb)   asm volatile("mbarrier.arrive.shared.b64 _, [%0];" :: "r"(mb) : "memory")
#define CP_ARRIVE(mb)   asm volatile("cp.async.mbarrier.arrive.noinc.shared.b64 [%0];" :: "r"(mb) : "memory")
#define MBAR_WAIT(mb, par) do {                                                \
    uint32_t _m = (mb); uint32_t _p = (par); uint32_t _d;                      \
    asm volatile("{ .reg .pred p; mbarrier.try_wait.parity.acquire.cta.shared::cta.b64 p, [%1], %2; selp.b32 %0, 1, 0, p; }" \
        : "=r"(_d) : "r"(_m), "r"(_p) : "memory");                             \
    if (!_d) {                                                                 \
        asm volatile("{ .reg .pred P1; WL%=: mbarrier.try_wait.parity.acquire.cta.shared::cta.b64 P1, [%0], %1, 0x989680;" \
            " @P1 bra.uni WD%=; bra.uni WL%=; WD%=: }" :: "r"(_m), "r"(_p) : "memory"); \
    } } while (0)

__device__ __forceinline__ uint32_t pack_h(__half a, __half b) {
    return ((uint32_t)__half_as_ushort(b) << 16) | __half_as_ushort(a);
}

// SMEM: toks @0 (512B), bias @512 (512B), wts @1024 (512B),
//       mbar full[3] @1536, empty[3] @1560, stages @2048.
// Stage (k-chunk 64 fp16 = 128B, pitch 144B): A @0 (128x144), B @18432.
// 3-stage ring: 2048 + 3*36864 = 112640 B/CTA -> 2 CTAs/SM.
#define SM_HDR  2048
#define PITCH   144
#define STG_SZ  36864
#define SMEM_DYN (SM_HDR + 3 * STG_SZ)

// ---------------- fused init + convert fp32 -> fp16 -------------------------
__global__ void k_split(const float* __restrict__ x, const float* __restrict__ w1,
                        const float* __restrict__ w2, float4* __restrict__ out4) {
    size_t stride = (size_t)gridDim.x * blockDim.x;
    size_t i0 = (size_t)blockIdx.x * blockDim.x + threadIdx.x;
    if (i0 < E_EXP) g_cnt[i0] = 0;
    const size_t no4 = (size_t)T_TOK * D_DIM / 4;
    float4 z = make_float4(0.f, 0.f, 0.f, 0.f);
    for (size_t i = i0; i < no4; i += stride) out4[i] = z;
    const size_t nx4 = (size_t)T_TOK * D_DIM / 4;
    const size_t nw4 = (size_t)E_EXP * F_DIM * D_DIM / 4;
    uint2* xo  = (uint2*)g_xh;
    uint2* w1o = (uint2*)g_w1h;
    uint2* w2o = (uint2*)g_w2h;
    for (size_t i = i0; i < nx4; i += stride) {
        float4 f = ((const float4*)x)[i];
        xo[i] = make_uint2(pack_h(__float2half_rn(f.x), __float2half_rn(f.y)),
                           pack_h(__float2half_rn(f.z), __float2half_rn(f.w)));
    }
    for (size_t i = i0; i < nw4; i += stride) {
        float4 f = ((const float4*)w1)[i];
        w1o[i] = make_uint2(pack_h(__float2half_rn(f.x), __float2half_rn(f.y)),
                            pack_h(__float2half_rn(f.z), __float2half_rn(f.w)));
    }
    for (size_t i = i0; i < nw4; i += stride) {
        float4 f = ((const float4*)w2)[i];
        w2o[i] = make_uint2(pack_h(__float2half_rn(f.x), __float2half_rn(f.y)),
                            pack_h(__float2half_rn(f.z), __float2half_rn(f.w)));
    }
}

// ---------------- gating (validated) ----------------------------------------
__global__ void k_gate(const float* __restrict__ x, const float* __restrict__ gw,
                       float* __restrict__ probs_out) {
    int warp = (blockIdx.x * blockDim.x + threadIdx.x) >> 5;
    int lane = threadIdx.x & 31;
    if (warp >= T_TOK) return;
    const float* xr = x + (size_t)warp * D_DIM;
    float acc[E_EXP];
#pragma unroll
    for (int e = 0; e < E_EXP; e++) acc[e] = 0.f;
    for (int k = lane * 4; k < D_DIM; k += 128) {
        float4 xv = *(const float4*)(xr + k);
#pragma unroll
        for (int e = 0; e < E_EXP; e++) {
            float4 wv = *(const float4*)(gw + (size_t)e * D_DIM + k);
            acc[e] += xv.x * wv.x + xv.y * wv.y + xv.z * wv.z + xv.w * wv.w;
        }
    }
#pragma unroll
    for (int e = 0; e < E_EXP; e++)
#pragma unroll
        for (int o = 16; o > 0; o >>= 1) acc[e] += __shfl_xor_sync(0xffffffffu, acc[e], o);
    if (lane == 0) {
        float mx = acc[0];
#pragma unroll
        for (int e = 1; e < E_EXP; e++) mx = fmaxf(mx, acc[e]);
        float p[E_EXP], s = 0.f;
#pragma unroll
        for (int e = 0; e < E_EXP; e++) { p[e] = expf(acc[e] - mx); s += p[e]; }
        float inv = 1.f / s;
#pragma unroll
        for (int e = 0; e < E_EXP; e++) {
            p[e] *= inv;
            probs_out[(size_t)warp * E_EXP + e] = p[e];
        }
        int i0 = 0;
#pragma unroll
        for (int e = 1; e < E_EXP; e++) if (p[e] > p[i0]) i0 = e;
        int i1 = (i0 == 0) ? 1 : 0;
#pragma unroll
        for (int e = 0; e < E_EXP; e++) if (e != i0 && p[e] > p[i1]) i1 = e;
        float denom = p[i0] + p[i1] + 1e-9f;
        int s0 = atomicAdd(&g_cnt[i0], 1);
        g_tok[i0 * T_TOK + s0] = warp; g_wt[i0 * T_TOK + s0] = p[i0] / denom;
        int s1 = atomicAdd(&g_cnt[i1], 1);
        g_tok[i1 * T_TOK + s1] = warp; g_wt[i1 * T_TOK + s1] = p[i1] / denom;
    }
}

// ---------------- inline prefix over 8 counters ------------------------------
__device__ __forceinline__ int expert_off(int e) {
    int off = 0;
#pragma unroll
    for (int i = 0; i < E_EXP - 1; ++i)
        if (i < e) off += g_cnt[i];
    return off;
}

// ---------------- GEMM core: block 128x128xk64, 8 warps, warp 32x64 ---------
#define LDM_SETUP()                                                            \
    const int lane = tid & 31, wid = tid >> 5;                                 \
    const int wm = (wid & 3) * 32, wn = (wid >> 2) * 64;                       \
    uint32_t aav[2];                                                           \
    _Pragma("unroll") for (int mt = 0; mt < 2; ++mt)                           \
        aav[mt] = sb + SM_HDR + (wm + mt * 16 + (lane & 15)) * PITCH +         \
                  ((lane >> 4) & 1) * 16;                                      \
    uint32_t bbv[4];                                                           \
    _Pragma("unroll") for (int g = 0; g < 4; ++g)                              \
        bbv[g] = sb + SM_HDR + 18432 +                                         \
            (wn + g * 16 + (lane & 7) + ((lane >> 4) & 1) * 8) * PITCH +       \
            ((lane >> 3) & 1) * 16;                                            \
    const uint32_t mbF0 = sb + 1536, mbF1 = sb + 1544, mbF2 = sb + 1552;       \
    const uint32_t mbE0 = sb + 1560, mbE1 = sb + 1568, mbE2 = sb + 1576;       \
    (void)mbF0; (void)mbF1; (void)mbF2; (void)mbE0; (void)mbE1; (void)mbE2;

// Fragment-pipelined chunk (validated R8): bit-identical per-accumulator order.
#define CHUNK(so) {                                                            \
    uint32_t Ah[2][2][4], Bh[2][4];                                            \
    LDX4(Ah[0][0], aav[0] + (so));                                             \
    LDX4(Ah[0][1], aav[1] + (so));                                             \
    LDX4(Bh[0], bbv[0] + (so));                                                \
    _Pragma("unroll") for (int kk = 0; kk < 4; ++kk) {                         \
        _Pragma("unroll") for (int g = 0; g < 4; ++g) {                        \
            const int cur = g & 1, nxt = cur ^ 1;                              \
            if (g < 3)       { LDX4(Bh[nxt], bbv[g + 1] + (so) + kk * 32); }   \
            else if (kk < 3) { LDX4(Bh[nxt], bbv[0] + (so) + (kk + 1) * 32); } \
            if (g == 0 && kk < 3) {                                            \
                LDX4(Ah[(kk + 1) & 1][0], aav[0] + (so) + (kk + 1) * 32);      \
                LDX4(Ah[(kk + 1) & 1][1], aav[1] + (so) + (kk + 1) * 32);      \
            }                                                                  \
            MMAH(acc[0][2 * g],     Ah[kk & 1][0], Bh[cur][0], Bh[cur][1]);    \
            MMAH(acc[1][2 * g],     Ah[kk & 1][1], Bh[cur][0], Bh[cur][1]);    \
            MMAH(acc[0][2 * g + 1], Ah[kk & 1][0], Bh[cur][2], Bh[cur][3]);    \
            MMAH(acc[1][2 * g + 1], Ah[kk & 1][1], Bh[cur][2], Bh[cur][3]);    \
        }                                                                      \
    }                                                                          \
}

#define ACC_INIT()                                                             \
    float acc[2][8][4];                                                        \
    _Pragma("unroll") for (int i = 0; i < 2; i++)                              \
        _Pragma("unroll") for (int j = 0; j < 8; j++)                          \
            _Pragma("unroll") for (int k = 0; k < 4; k++) acc[i][j][k] = 0.f;

// mbarrier ring iteration. J = cc%3 buffer (compile-time), JS = (J+2)%3 stage
// buffer, PF = (cc/3)&1 full-parity, PE = empty-parity for stage cc+2.
// Producer: wait empty[JS] (unless first use), stage cc+2, async-arrive full[JS].
// Consumer: wait full[J], CHUNK, arrive empty[J]. No __syncthreads — warps drift.
#define MB_ITER(STAGE, cc, J, JS, PF, PE)                                      \
    if ((cc) < NC) {                                                           \
        if ((cc) + 2 < NC) {                                                   \
            if ((cc) >= 1) MBAR_WAIT(mbE##JS, PE);                             \
            STAGE((cc) + 2, (JS) * STG_SZ);                                    \
            CP_ARRIVE(mbF##JS);                                                \
        }                                                                      \
        MBAR_WAIT(mbF##J, PF);                                                 \
        CHUNK((J) * STG_SZ);                                                   \
        MB_ARRIVE(mbE##J);                                                     \
    }

#define MB_LOOP(STAGE)                                                         \
    for (int cb = 0; cb < NC; cb += 6) {                                       \
        MB_ITER(STAGE, cb + 0, 0, 2, 0, 1);                                    \
        MB_ITER(STAGE, cb + 1, 1, 0, 0, 0);                                    \
        MB_ITER(STAGE, cb + 2, 2, 1, 0, 0);                                    \
        MB_ITER(STAGE, cb + 3, 0, 2, 1, 0);                                    \
        MB_ITER(STAGE, cb + 4, 1, 0, 1, 1);                                    \
        MB_ITER(STAGE, cb + 5, 2, 1, 1, 1);                                    \
    }

// ---------------- fc1: h = gelu(X[gather] @ W1e^T + b1) -> fp16 -------------
__global__ __launch_bounds__(256, 2) void k_fc1_h(const float* __restrict__ b1) {
    const int e = blockIdx.z;
    const int cnt = g_cnt[e];
    const int m0 = blockIdx.y * 128;
    if (m0 >= cnt) return;
    const int n0 = blockIdx.x * 128;

    extern __shared__ __align__(128) char smp[];
    const uint32_t sb = smem_u32(smp);
    int*   toks_s = (int*)smp;
    float* bias_s = (float*)(smp + 512);
    const int tid = threadIdx.x;
    if (tid < 128) {
        toks_s[tid] = g_tok[e * T_TOK + min(m0 + tid, cnt - 1)];
        bias_s[tid] = b1[e * F_DIM + n0 + tid];
    }
    if (tid == 0) {
#pragma unroll
        for (int j = 0; j < 3; ++j) {
            MB_INIT(sb + 1536 + j * 8, 256);
            MB_INIT(sb + 1560 + j * 8, 256);
        }
    }
    __syncthreads();

    // staging: q = tid&7 (16B quad of 128B row), r = tid>>3 (0..31), rows r+32j
    const int q = tid & 7, r = tid >> 3;
    const uint32_t dA = sb + SM_HDR + r * PITCH + q * 16;
    const uint32_t dB = dA + 18432;
    const char* xp = (const char*)g_xh;
    size_t aoff[4];
    const char* wp[4];
#pragma unroll
    for (int j = 0; j < 4; ++j) {
        aoff[j] = (size_t)toks_s[r + 32 * j] * (D_DIM * 2) + q * 16;
        wp[j] = (const char*)(g_w1h + ((size_t)e * F_DIM + n0 + r + 32 * j) * D_DIM) + q * 16;
    }

#define STAGE1(c, so) { const uint32_t ko = (uint32_t)(c) * 128;               \
    _Pragma("unroll") for (int j = 0; j < 4; ++j) {                            \
        CP16(dA + (so) + j * (32 * PITCH), xp + aoff[j] + ko);                 \
        CP16(dB + (so) + j * (32 * PITCH), wp[j] + ko);                        \
    } }

    LDM_SETUP();
    ACC_INIT();

    const int NC = D_DIM / 64;  // 16
    STAGE1(0, 0);          CP_ARRIVE(mbF0);
    STAGE1(1, STG_SZ);     CP_ARRIVE(mbF1);
    MB_LOOP(STAGE1);

    // epilogue: bias + exact gelu -> fp16 -> g_hh
    const int gid2 = lane >> 2, tg = lane & 3;
    const int hbase = expert_off(e) + m0;
    uint32_t* gh = (uint32_t*)g_hh;
#pragma unroll
    for (int mt = 0; mt < 2; ++mt)
#pragma unroll
        for (int nt = 0; nt < 8; ++nt) {
            const int n = wn + nt * 8 + tg * 2;
            const float bv0 = bias_s[n], bv1 = bias_s[n + 1];
#pragma unroll
            for (int h = 0; h < 2; ++h) {
                const int m = wm + mt * 16 + gid2 + h * 8;
                if (m0 + m < cnt) {
                    float v0 = acc[mt][nt][2 * h + 0] + bv0;
                    float v1 = acc[mt][nt][2 * h + 1] + bv1;
                    v0 = 0.5f * v0 * (1.f + erff(v0 * 0.7071067811865476f));
                    v1 = 0.5f * v1 * (1.f + erff(v1 * 0.7071067811865476f));
                    gh[(size_t)(hbase + m) * (F_DIM / 2) + (size_t)(n0 + n) / 2] =
                        pack_h(__float2half_rn(v0), __float2half_rn(v1));
                }
            }
        }
}

// ---------------- fc2: out[tok] += w * (H @ W2e^T + b2) ---------------------
__global__ __launch_bounds__(256, 2) void k_fc2_h(const float* __restrict__ b2,
                                                  float* __restrict__ out) {
    const int e = blockIdx.z;
    const int cnt = g_cnt[e];
    const int m0 = blockIdx.y * 128;
    if (m0 >= cnt) return;
    const int n0 = blockIdx.x * 128;

    extern __shared__ __align__(128) char smp[];
    const uint32_t sb = smem_u32(smp);
    int*   toks_s = (int*)smp;
    float* bias_s = (float*)(smp + 512);
    float* wts_s  = (float*)(smp + 1024);
    const int tid = threadIdx.x;
    if (tid < 128) {
        const int sl = min(m0 + tid, cnt - 1);
        toks_s[tid] = g_tok[e * T_TOK + sl];
        wts_s[tid]  = g_wt [e * T_TOK + sl];
        bias_s[tid] = b2[e * D_DIM + n0 + tid];
    }
    if (tid == 0) {
#pragma unroll
        for (int j = 0; j < 3; ++j) {
            MB_INIT(sb + 1536 + j * 8, 256);
            MB_INIT(sb + 1560 + j * 8, 256);
        }
    }
    __syncthreads();

    const int q = tid & 7, r = tid >> 3;
    const uint32_t dA = sb + SM_HDR + r * PITCH + q * 16;
    const uint32_t dB = dA + 18432;
    const char* hp = (const char*)g_hh;
    const int off = expert_off(e);
    size_t aoff[4];
    const char* wp[4];
#pragma unroll
    for (int j = 0; j < 4; ++j) {
        aoff[j] = (size_t)(off + min(m0 + r + 32 * j, cnt - 1)) * (F_DIM * 2) + q * 16;
        wp[j] = (const char*)(g_w2h + ((size_t)e * D_DIM + n0 + r + 32 * j) * F_DIM) + q * 16;
    }

#define STAGE2(c, so) { const uint32_t ko = (uint32_t)(c) * 128;               \
    _Pragma("unroll") for (int j = 0; j < 4; ++j) {                            \
        CP16(dA + (so) + j * (32 * PITCH), hp + aoff[j] + ko);                 \
        CP16(dB + (so) + j * (32 * PITCH), wp[j] + ko);                        \
    } }

    LDM_SETUP();
    ACC_INIT();

    const int NC = F_DIM / 64;  // 64
    STAGE2(0, 0);          CP_ARRIVE(mbF0);
    STAGE2(1, STG_SZ);     CP_ARRIVE(mbF1);
    MB_LOOP(STAGE2);

    // epilogue: (acc + bias) * wt -> atomicAdd scatter (2 adds/elem onto 0)
    const int gid2 = lane >> 2, tg = lane & 3;
#pragma unroll
    for (int mt = 0; mt < 2; ++mt)
#pragma unroll
        for (int nt = 0; nt < 8; ++nt) {
            const int n = wn + nt * 8 + tg * 2;
            const float bv0 = bias_s[n], bv1 = bias_s[n + 1];
#pragma unroll
            for (int h = 0; h < 2; ++h) {
                const int m = wm + mt * 16 + gid2 + h * 8;
                if (m0 + m < cnt) {
                    const int   t = toks_s[m];
                    const float w = wts_s[m];
                    float* op = out + (size_t)t * D_DIM + n0 + n;
                    atomicAdd(op,     (acc[mt][nt][2 * h + 0] + bv0) * w);
                    atomicAdd(op + 1, (acc[mt][nt][2 * h + 1] + bv1) * w);
                }
            }
        }
}

// ---------------- launch -----------------------------------------------------
extern "C" void kernel_launch(void* const* d_in, const int* in_sizes, int n_in,
                              void* d_out, int out_size) {
    const float* x  = (const float*)d_in[0];
    const float* gw = (const float*)d_in[1];
    const float* w1 = (const float*)d_in[2];
    const float* b1 = (const float*)d_in[3];
    const float* w2 = (const float*)d_in[4];
    const float* b2 = (const float*)d_in[5];
    float* out   = (float*)d_out;
    float* probs = out + (size_t)T_TOK * D_DIM;

    cudaFuncSetAttribute(k_fc1_h, cudaFuncAttributeMaxDynamicSharedMemorySize, SMEM_DYN);
    cudaFuncSetAttribute(k_fc2_h, cudaFuncAttributeMaxDynamicSharedMemorySize, SMEM_DYN);

    k_split<<<1024, 256>>>(x, w1, w2, (float4*)out);
    k_gate<<<T_TOK / 8, 256>>>(x, gw, probs);
    k_fc1_h<<<dim3(F_DIM / 128, T_TOK / 128, E_EXP), 256, SMEM_DYN>>>(b1);
    k_fc2_h<<<dim3(D_DIM / 128, T_TOK / 128, E_EXP), 256, SMEM_DYN>>>(b2, out);
}

// round 13
// speedup vs baseline: 1.3887x; 1.0668x over previous
#include <cuda_runtime.h>
#include <cuda_fp16.h>
#include <math.h>
#include <stdint.h>

#define T_TOK 8192
#define D_DIM 1024
#define F_DIM 4096
#define E_EXP 8

// ---------------- scratch (static device globals; no allocations) ----------
__device__ int    g_cnt[E_EXP];
__device__ int    g_tok[E_EXP * T_TOK];
__device__ float  g_wt [E_EXP * T_TOK];

__device__ __half g_xh [(size_t)T_TOK * D_DIM];
__device__ __half g_w1h[(size_t)E_EXP * F_DIM * D_DIM];
__device__ __half g_w2h[(size_t)E_EXP * D_DIM * F_DIM];
__device__ __half g_hh [(size_t)2 * T_TOK * F_DIM];

// ---------------- PTX helpers (sm_80+ features only) ------------------------
__device__ __forceinline__ uint32_t smem_u32(const void* p) {
    uint32_t a;
    asm("{ .reg .u64 t; cvta.to.shared.u64 t, %1; cvt.u32.u64 %0, t; }" : "=r"(a) : "l"(p));
    return a;
}
#define CP16(dst, src) asm volatile("cp.async.cg.shared.global [%0], [%1], 16;" :: "r"(dst), "l"(src) : "memory")
#define LDX4(r, a)                                                             \
    asm volatile("ldmatrix.sync.aligned.m8n8.x4.shared.b16 {%0,%1,%2,%3}, [%4];" \
        : "=r"((r)[0]), "=r"((r)[1]), "=r"((r)[2]), "=r"((r)[3]) : "r"(a))
#define MMAH(d, a, b0, b1)                                                     \
    asm volatile("mma.sync.aligned.m16n8k16.row.col.f32.f16.f16.f32 "          \
        "{%0,%1,%2,%3},{%4,%5,%6,%7},{%8,%9},{%0,%1,%2,%3};"                   \
        : "+f"((d)[0]), "+f"((d)[1]), "+f"((d)[2]), "+f"((d)[3])               \
        : "r"((a)[0]), "r"((a)[1]), "r"((a)[2]), "r"((a)[3]), "r"(b0), "r"(b1))

// mbarrier flow control (sm_80 mbarrier + cp.async integration)
#define MB_INIT(mb, c)  asm volatile("mbarrier.init.shared.b64 [%0], %1;" :: "r"(mb), "r"(c) : "memory")
#define MB_ARRIVE(mb)   asm volatile("mbarrier.arrive.shared.b64 _, [%0];" :: "r"(mb) : "memory")
#define CP_ARRIVE(mb)   asm volatile("cp.async.mbarrier.arrive.noinc.shared.b64 [%0];" :: "r"(mb) : "memory")
#define MBAR_WAIT(mb, par) do {                                                \
    uint32_t _m = (mb); uint32_t _p = (par); uint32_t _d;                      \
    asm volatile("{ .reg .pred p; mbarrier.try_wait.parity.acquire.cta.shared::cta.b64 p, [%1], %2; selp.b32 %0, 1, 0, p; }" \
        : "=r"(_d) : "r"(_m), "r"(_p) : "memory");                             \
    if (!_d) {                                                                 \
        asm volatile("{ .reg .pred P1; WL%=: mbarrier.try_wait.parity.acquire.cta.shared::cta.b64 P1, [%0], %1, 0x989680;" \
            " @P1 bra.uni WD%=; bra.uni WL%=; WD%=: }" :: "r"(_m), "r"(_p) : "memory"); \
    } } while (0)

__device__ __forceinline__ uint32_t pack_h(__half a, __half b) {
    return ((uint32_t)__half_as_ushort(b) << 16) | __half_as_ushort(a);
}

// SMEM: toks @0 (512B), bias @512 (512B), wts @1024 (512B),
//       mbar full[3] @1536, empty[3] @1560, stages @2048.
// Stage (k-chunk 64 fp16 = 128B, pitch 144B): A @0 (128x144), B @18432.
// 3-stage ring: 2048 + 3*36864 = 112640 B/CTA -> 2 CTAs/SM.
#define SM_HDR  2048
#define PITCH   144
#define STG_SZ  36864
#define SMEM_DYN (SM_HDR + 3 * STG_SZ)

// ---------------- fused init + convert fp32 -> fp16 -------------------------
__global__ void k_split(const float* __restrict__ x, const float* __restrict__ w1,
                        const float* __restrict__ w2, float4* __restrict__ out4) {
    size_t stride = (size_t)gridDim.x * blockDim.x;
    size_t i0 = (size_t)blockIdx.x * blockDim.x + threadIdx.x;
    if (i0 < E_EXP) g_cnt[i0] = 0;
    const size_t no4 = (size_t)T_TOK * D_DIM / 4;
    float4 z = make_float4(0.f, 0.f, 0.f, 0.f);
    for (size_t i = i0; i < no4; i += stride) out4[i] = z;
    const size_t nx4 = (size_t)T_TOK * D_DIM / 4;
    const size_t nw4 = (size_t)E_EXP * F_DIM * D_DIM / 4;
    uint2* xo  = (uint2*)g_xh;
    uint2* w1o = (uint2*)g_w1h;
    uint2* w2o = (uint2*)g_w2h;
    for (size_t i = i0; i < nx4; i += stride) {
        float4 f = ((const float4*)x)[i];
        xo[i] = make_uint2(pack_h(__float2half_rn(f.x), __float2half_rn(f.y)),
                           pack_h(__float2half_rn(f.z), __float2half_rn(f.w)));
    }
    for (size_t i = i0; i < nw4; i += stride) {
        float4 f = ((const float4*)w1)[i];
        w1o[i] = make_uint2(pack_h(__float2half_rn(f.x), __float2half_rn(f.y)),
                            pack_h(__float2half_rn(f.z), __float2half_rn(f.w)));
    }
    for (size_t i = i0; i < nw4; i += stride) {
        float4 f = ((const float4*)w2)[i];
        w2o[i] = make_uint2(pack_h(__float2half_rn(f.x), __float2half_rn(f.y)),
                            pack_h(__float2half_rn(f.z), __float2half_rn(f.w)));
    }
}

// ---------------- gating (validated) ----------------------------------------
__global__ void k_gate(const float* __restrict__ x, const float* __restrict__ gw,
                       float* __restrict__ probs_out) {
    int warp = (blockIdx.x * blockDim.x + threadIdx.x) >> 5;
    int lane = threadIdx.x & 31;
    if (warp >= T_TOK) return;
    const float* xr = x + (size_t)warp * D_DIM;
    float acc[E_EXP];
#pragma unroll
    for (int e = 0; e < E_EXP; e++) acc[e] = 0.f;
    for (int k = lane * 4; k < D_DIM; k += 128) {
        float4 xv = *(const float4*)(xr + k);
#pragma unroll
        for (int e = 0; e < E_EXP; e++) {
            float4 wv = *(const float4*)(gw + (size_t)e * D_DIM + k);
            acc[e] += xv.x * wv.x + xv.y * wv.y + xv.z * wv.z + xv.w * wv.w;
        }
    }
#pragma unroll
    for (int e = 0; e < E_EXP; e++)
#pragma unroll
        for (int o = 16; o > 0; o >>= 1) acc[e] += __shfl_xor_sync(0xffffffffu, acc[e], o);
    if (lane == 0) {
        float mx = acc[0];
#pragma unroll
        for (int e = 1; e < E_EXP; e++) mx = fmaxf(mx, acc[e]);
        float p[E_EXP], s = 0.f;
#pragma unroll
        for (int e = 0; e < E_EXP; e++) { p[e] = expf(acc[e] - mx); s += p[e]; }
        float inv = 1.f / s;
#pragma unroll
        for (int e = 0; e < E_EXP; e++) {
            p[e] *= inv;
            probs_out[(size_t)warp * E_EXP + e] = p[e];
        }
        int i0 = 0;
#pragma unroll
        for (int e = 1; e < E_EXP; e++) if (p[e] > p[i0]) i0 = e;
        int i1 = (i0 == 0) ? 1 : 0;
#pragma unroll
        for (int e = 0; e < E_EXP; e++) if (e != i0 && p[e] > p[i1]) i1 = e;
        float denom = p[i0] + p[i1] + 1e-9f;
        int s0 = atomicAdd(&g_cnt[i0], 1);
        g_tok[i0 * T_TOK + s0] = warp; g_wt[i0 * T_TOK + s0] = p[i0] / denom;
        int s1 = atomicAdd(&g_cnt[i1], 1);
        g_tok[i1 * T_TOK + s1] = warp; g_wt[i1 * T_TOK + s1] = p[i1] / denom;
    }
}

// ---------------- inline prefix over 8 counters ------------------------------
__device__ __forceinline__ int expert_off(int e) {
    int off = 0;
#pragma unroll
    for (int i = 0; i < E_EXP - 1; ++i)
        if (i < e) off += g_cnt[i];
    return off;
}

// ---------------- GEMM core: block 128x128xk64, 8 warps, warp 32x64 ---------
#define LDM_SETUP()                                                            \
    const int lane = tid & 31, wid = tid >> 5;                                 \
    const int wm = (wid & 3) * 32, wn = (wid >> 2) * 64;                       \
    uint32_t aav[2];                                                           \
    _Pragma("unroll") for (int mt = 0; mt < 2; ++mt)                           \
        aav[mt] = sb + SM_HDR + (wm + mt * 16 + (lane & 15)) * PITCH +         \
                  ((lane >> 4) & 1) * 16;                                      \
    uint32_t bbv[4];                                                           \
    _Pragma("unroll") for (int g = 0; g < 4; ++g)                              \
        bbv[g] = sb + SM_HDR + 18432 +                                         \
            (wn + g * 16 + (lane & 7) + ((lane >> 4) & 1) * 8) * PITCH +       \
            ((lane >> 3) & 1) * 16;                                            \
    const uint32_t mbF0 = sb + 1536, mbF1 = sb + 1544, mbF2 = sb + 1552;       \
    const uint32_t mbE0 = sb + 1560, mbE1 = sb + 1568, mbE2 = sb + 1576;       \
    (void)mbF0; (void)mbF1; (void)mbF2; (void)mbE0; (void)mbE1; (void)mbE2;

// Fragment-pipelined chunk (validated R8): bit-identical per-accumulator order.
#define CHUNK(so) {                                                            \
    uint32_t Ah[2][2][4], Bh[2][4];                                            \
    LDX4(Ah[0][0], aav[0] + (so));                                             \
    LDX4(Ah[0][1], aav[1] + (so));                                             \
    LDX4(Bh[0], bbv[0] + (so));                                                \
    _Pragma("unroll") for (int kk = 0; kk < 4; ++kk) {                         \
        _Pragma("unroll") for (int g = 0; g < 4; ++g) {                        \
            const int cur = g & 1, nxt = cur ^ 1;                              \
            if (g < 3)       { LDX4(Bh[nxt], bbv[g + 1] + (so) + kk * 32); }   \
            else if (kk < 3) { LDX4(Bh[nxt], bbv[0] + (so) + (kk + 1) * 32); } \
            if (g == 0 && kk < 3) {                                            \
                LDX4(Ah[(kk + 1) & 1][0], aav[0] + (so) + (kk + 1) * 32);      \
                LDX4(Ah[(kk + 1) & 1][1], aav[1] + (so) + (kk + 1) * 32);      \
            }                                                                  \
            MMAH(acc[0][2 * g],     Ah[kk & 1][0], Bh[cur][0], Bh[cur][1]);    \
            MMAH(acc[1][2 * g],     Ah[kk & 1][1], Bh[cur][0], Bh[cur][1]);    \
            MMAH(acc[0][2 * g + 1], Ah[kk & 1][0], Bh[cur][2], Bh[cur][3]);    \
            MMAH(acc[1][2 * g + 1], Ah[kk & 1][1], Bh[cur][2], Bh[cur][3]);    \
        }                                                                      \
    }                                                                          \
}

#define ACC_INIT()                                                             \
    float acc[2][8][4];                                                        \
    _Pragma("unroll") for (int i = 0; i < 2; i++)                              \
        _Pragma("unroll") for (int j = 0; j < 8; j++)                          \
            _Pragma("unroll") for (int k = 0; k < 4; k++) acc[i][j][k] = 0.f;

// Consumer-first mbarrier ring iteration (same barrier/parity schedule as R12,
// re-ordered within the iteration): wait full -> CHUNK -> lane0 arrives empty
// (count 8) -> producer stages chunk cc+2 in the shadow of other warps' MMAs.
#define MB_ITER(STAGE, cc, J, JS, PF, PE)                                      \
    if ((cc) < NC) {                                                           \
        MBAR_WAIT(mbF##J, PF);                                                 \
        CHUNK((J) * STG_SZ);                                                   \
        if (lane == 0) MB_ARRIVE(mbE##J);                                      \
        if ((cc) + 2 < NC) {                                                   \
            if ((cc) >= 1) MBAR_WAIT(mbE##JS, PE);                             \
            STAGE((cc) + 2, (JS) * STG_SZ);                                    \
            CP_ARRIVE(mbF##JS);                                                \
        }                                                                      \
    }

#define MB_LOOP(STAGE)                                                         \
    for (int cb = 0; cb < NC; cb += 6) {                                       \
        MB_ITER(STAGE, cb + 0, 0, 2, 0, 1);                                    \
        MB_ITER(STAGE, cb + 1, 1, 0, 0, 0);                                    \
        MB_ITER(STAGE, cb + 2, 2, 1, 0, 0);                                    \
        MB_ITER(STAGE, cb + 3, 0, 2, 1, 0);                                    \
        MB_ITER(STAGE, cb + 4, 1, 0, 1, 1);                                    \
        MB_ITER(STAGE, cb + 5, 2, 1, 1, 1);                                    \
    }

// ---------------- fc1: h = gelu(X[gather] @ W1e^T + b1) -> fp16 -------------
__global__ __launch_bounds__(256, 2) void k_fc1_h(const float* __restrict__ b1) {
    const int e = blockIdx.z;
    const int cnt = g_cnt[e];
    const int m0 = blockIdx.y * 128;
    if (m0 >= cnt) return;
    const int n0 = blockIdx.x * 128;

    extern __shared__ __align__(128) char smp[];
    const uint32_t sb = smem_u32(smp);
    int*   toks_s = (int*)smp;
    float* bias_s = (float*)(smp + 512);
    const int tid = threadIdx.x;
    if (tid < 128) {
        toks_s[tid] = g_tok[e * T_TOK + min(m0 + tid, cnt - 1)];
        bias_s[tid] = b1[e * F_DIM + n0 + tid];
    }
    if (tid == 0) {
#pragma unroll
        for (int j = 0; j < 3; ++j) {
            MB_INIT(sb + 1536 + j * 8, 256);  // full: all threads' cp.async
            MB_INIT(sb + 1560 + j * 8, 8);    // empty: one arrive per warp
        }
    }
    __syncthreads();

    // staging: q = tid&7 (16B quad of 128B row), r = tid>>3 (0..31), rows r+32j
    const int q = tid & 7, r = tid >> 3;
    const uint32_t dA = sb + SM_HDR + r * PITCH + q * 16;
    const uint32_t dB = dA + 18432;
    const char* xp = (const char*)g_xh;
    size_t aoff[4];
    const char* wp[4];
#pragma unroll
    for (int j = 0; j < 4; ++j) {
        aoff[j] = (size_t)toks_s[r + 32 * j] * (D_DIM * 2) + q * 16;
        wp[j] = (const char*)(g_w1h + ((size_t)e * F_DIM + n0 + r + 32 * j) * D_DIM) + q * 16;
    }

#define STAGE1(c, so) { const uint32_t ko = (uint32_t)(c) * 128;               \
    _Pragma("unroll") for (int j = 0; j < 4; ++j) {                            \
        CP16(dA + (so) + j * (32 * PITCH), xp + aoff[j] + ko);                 \
        CP16(dB + (so) + j * (32 * PITCH), wp[j] + ko);                        \
    } }

    LDM_SETUP();
    ACC_INIT();

    const int NC = D_DIM / 64;  // 16
    STAGE1(0, 0);          CP_ARRIVE(mbF0);
    STAGE1(1, STG_SZ);     CP_ARRIVE(mbF1);
    MB_LOOP(STAGE1);

    // epilogue: bias + exact gelu -> fp16 -> g_hh
    const int gid2 = lane >> 2, tg = lane & 3;
    const int hbase = expert_off(e) + m0;
    uint32_t* gh = (uint32_t*)g_hh;
#pragma unroll
    for (int mt = 0; mt < 2; ++mt)
#pragma unroll
        for (int nt = 0; nt < 8; ++nt) {
            const int n = wn + nt * 8 + tg * 2;
            const float bv0 = bias_s[n], bv1 = bias_s[n + 1];
#pragma unroll
            for (int h = 0; h < 2; ++h) {
                const int m = wm + mt * 16 + gid2 + h * 8;
                if (m0 + m < cnt) {
                    float v0 = acc[mt][nt][2 * h + 0] + bv0;
                    float v1 = acc[mt][nt][2 * h + 1] + bv1;
                    v0 = 0.5f * v0 * (1.f + erff(v0 * 0.7071067811865476f));
                    v1 = 0.5f * v1 * (1.f + erff(v1 * 0.7071067811865476f));
                    gh[(size_t)(hbase + m) * (F_DIM / 2) + (size_t)(n0 + n) / 2] =
                        pack_h(__float2half_rn(v0), __float2half_rn(v1));
                }
            }
        }
}

// ---------------- fc2: out[tok] += w * (H @ W2e^T + b2) ---------------------
__global__ __launch_bounds__(256, 2) void k_fc2_h(const float* __restrict__ b2,
                                                  float* __restrict__ out) {
    const int e = blockIdx.z;
    const int cnt = g_cnt[e];
    const int m0 = blockIdx.y * 128;
    if (m0 >= cnt) return;
    const int n0 = blockIdx.x * 128;

    extern __shared__ __align__(128) char smp[];
    const uint32_t sb = smem_u32(smp);
    int*   toks_s = (int*)smp;
    float* bias_s = (float*)(smp + 512);
    float* wts_s  = (float*)(smp + 1024);
    const int tid = threadIdx.x;
    if (tid < 128) {
        const int sl = min(m0 + tid, cnt - 1);
        toks_s[tid] = g_tok[e * T_TOK + sl];
        wts_s[tid]  = g_wt [e * T_TOK + sl];
        bias_s[tid] = b2[e * D_DIM + n0 + tid];
    }
    if (tid == 0) {
#pragma unroll
        for (int j = 0; j < 3; ++j) {
            MB_INIT(sb + 1536 + j * 8, 256);
            MB_INIT(sb + 1560 + j * 8, 8);
        }
    }
    __syncthreads();

    const int q = tid & 7, r = tid >> 3;
    const uint32_t dA = sb + SM_HDR + r * PITCH + q * 16;
    const uint32_t dB = dA + 18432;
    const char* hp = (const char*)g_hh;
    const int off = expert_off(e);
    size_t aoff[4];
    const char* wp[4];
#pragma unroll
    for (int j = 0; j < 4; ++j) {
        aoff[j] = (size_t)(off + min(m0 + r + 32 * j, cnt - 1)) * (F_DIM * 2) + q * 16;
        wp[j] = (const char*)(g_w2h + ((size_t)e * D_DIM + n0 + r + 32 * j) * F_DIM) + q * 16;
    }

#define STAGE2(c, so) { const uint32_t ko = (uint32_t)(c) * 128;               \
    _Pragma("unroll") for (int j = 0; j < 4; ++j) {                            \
        CP16(dA + (so) + j * (32 * PITCH), hp + aoff[j] + ko);                 \
        CP16(dB + (so) + j * (32 * PITCH), wp[j] + ko);                        \
    } }

    LDM_SETUP();
    ACC_INIT();

    const int NC = F_DIM / 64;  // 64
    STAGE2(0, 0);          CP_ARRIVE(mbF0);
    STAGE2(1, STG_SZ);     CP_ARRIVE(mbF1);
    MB_LOOP(STAGE2);

    // epilogue: (acc + bias) * wt -> atomicAdd scatter (2 adds/elem onto 0)
    const int gid2 = lane >> 2, tg = lane & 3;
#pragma unroll
    for (int mt = 0; mt < 2; ++mt)
#pragma unroll
        for (int nt = 0; nt < 8; ++nt) {
            const int n = wn + nt * 8 + tg * 2;
            const float bv0 = bias_s[n], bv1 = bias_s[n + 1];
#pragma unroll
            for (int h = 0; h < 2; ++h) {
                const int m = wm + mt * 16 + gid2 + h * 8;
                if (m0 + m < cnt) {
                    const int   t = toks_s[m];
                    const float w = wts_s[m];
                    float* op = out + (size_t)t * D_DIM + n0 + n;
                    atomicAdd(op,     (acc[mt][nt][2 * h + 0] + bv0) * w);
                    atomicAdd(op + 1, (acc[mt][nt][2 * h + 1] + bv1) * w);
                }
            }
        }
}

// ---------------- launch -----------------------------------------------------
extern "C" void kernel_launch(void* const* d_in, const int* in_sizes, int n_in,
                              void* d_out, int out_size) {
    const float* x  = (const float*)d_in[0];
    const float* gw = (const float*)d_in[1];
    const float* w1 = (const float*)d_in[2];
    const float* b1 = (const float*)d_in[3];
    const float* w2 = (const float*)d_in[4];
    const float* b2 = (const float*)d_in[5];
    float* out   = (float*)d_out;
    float* probs = out + (size_t)T_TOK * D_DIM;

    cudaFuncSetAttribute(k_fc1_h, cudaFuncAttributeMaxDynamicSharedMemorySize, SMEM_DYN);
    cudaFuncSetAttribute(k_fc2_h, cudaFuncAttributeMaxDynamicSharedMemorySize, SMEM_DYN);

    k_split<<<1024, 256>>>(x, w1, w2, (float4*)out);
    k_gate<<<T_TOK / 8, 256>>>(x, gw, probs);
    k_fc1_h<<<dim3(F_DIM / 128, T_TOK / 128, E_EXP), 256, SMEM_DYN>>>(b1);
    k_fc2_h<<<dim3(D_DIM / 128, T_TOK / 128, E_EXP), 256, SMEM_DYN>>>(b2, out);
}

// round 14
// speedup vs baseline: 1.4151x; 1.0190x over previous
#include <cuda_runtime.h>
#include <cuda_fp16.h>
#include <math.h>
#include <stdint.h>

#define T_TOK 8192
#define D_DIM 1024
#define F_DIM 4096
#define E_EXP 8

// ---------------- scratch (static device globals; no allocations) ----------
__device__ int    g_cnt[E_EXP];
__device__ int    g_tok[E_EXP * T_TOK];
__device__ float  g_wt [E_EXP * T_TOK];

__device__ __half g_xh [(size_t)T_TOK * D_DIM];
__device__ __half g_w1h[(size_t)E_EXP * F_DIM * D_DIM];
__device__ __half g_w2h[(size_t)E_EXP * D_DIM * F_DIM];
__device__ __half g_hh [(size_t)2 * T_TOK * F_DIM];

// ---------------- PTX helpers (sm_80+ features only) ------------------------
__device__ __forceinline__ uint32_t smem_u32(const void* p) {
    uint32_t a;
    asm("{ .reg .u64 t; cvta.to.shared.u64 t, %1; cvt.u32.u64 %0, t; }" : "=r"(a) : "l"(p));
    return a;
}
#define CP16(dst, src) asm volatile("cp.async.cg.shared.global [%0], [%1], 16;" :: "r"(dst), "l"(src) : "memory")
#define LDX4(r, a)                                                             \
    asm volatile("ldmatrix.sync.aligned.m8n8.x4.shared.b16 {%0,%1,%2,%3}, [%4];" \
        : "=r"((r)[0]), "=r"((r)[1]), "=r"((r)[2]), "=r"((r)[3]) : "r"(a))
#define MMAH(d, a, b0, b1)                                                     \
    asm volatile("mma.sync.aligned.m16n8k16.row.col.f32.f16.f16.f32 "          \
        "{%0,%1,%2,%3},{%4,%5,%6,%7},{%8,%9},{%0,%1,%2,%3};"                   \
        : "+f"((d)[0]), "+f"((d)[1]), "+f"((d)[2]), "+f"((d)[3])               \
        : "r"((a)[0]), "r"((a)[1]), "r"((a)[2]), "r"((a)[3]), "r"(b0), "r"(b1))

// mbarrier flow control (sm_80 mbarrier + cp.async integration)
#define MB_INIT(mb, c)  asm volatile("mbarrier.init.shared.b64 [%0], %1;" :: "r"(mb), "r"(c) : "memory")
#define MB_ARRIVE(mb)   asm volatile("mbarrier.arrive.shared.b64 _, [%0];" :: "r"(mb) : "memory")
#define CP_ARRIVE(mb)   asm volatile("cp.async.mbarrier.arrive.noinc.shared.b64 [%0];" :: "r"(mb) : "memory")
#define MBAR_WAIT(mb, par) do {                                                \
    uint32_t _m = (mb); uint32_t _p = (par); uint32_t _d;                      \
    asm volatile("{ .reg .pred p; mbarrier.try_wait.parity.acquire.cta.shared::cta.b64 p, [%1], %2; selp.b32 %0, 1, 0, p; }" \
        : "=r"(_d) : "r"(_m), "r"(_p) : "memory");                             \
    if (!_d) {                                                                 \
        asm volatile("{ .reg .pred P1; WL%=: mbarrier.try_wait.parity.acquire.cta.shared::cta.b64 P1, [%0], %1, 0x989680;" \
            " @P1 bra.uni WD%=; bra.uni WL%=; WD%=: }" :: "r"(_m), "r"(_p) : "memory"); \
    } } while (0)
// Relaxed wait: producer-side only — every post-wait access to the buffer is
// async-proxy (cp.async), ordered by its own mechanism. Consumers keep .acquire.
#define MBAR_WAIT_RLX(mb, par) do {                                            \
    uint32_t _m = (mb); uint32_t _p = (par); uint32_t _d;                      \
    asm volatile("{ .reg .pred p; mbarrier.try_wait.parity.relaxed.cta.shared::cta.b64 p, [%1], %2; selp.b32 %0, 1, 0, p; }" \
        : "=r"(_d) : "r"(_m), "r"(_p) : "memory");                             \
    if (!_d) {                                                                 \
        asm volatile("{ .reg .pred P1; WL%=: mbarrier.try_wait.parity.relaxed.cta.shared::cta.b64 P1, [%0], %1, 0x989680;" \
            " @P1 bra.uni WD%=; bra.uni WL%=; WD%=: }" :: "r"(_m), "r"(_p) : "memory"); \
    } } while (0)

__device__ __forceinline__ uint32_t pack_h(__half a, __half b) {
    return ((uint32_t)__half_as_ushort(b) << 16) | __half_as_ushort(a);
}

// SMEM: toks @0 (512B), bias @512 (512B), wts @1024 (512B),
//       mbar full[3] @1536, empty[3] @1560, stages @2048.
// Stage (k-chunk 64 fp16 = 128B, pitch 144B): A @0 (128x144), B @18432.
// 3-stage ring: 2048 + 3*36864 = 112640 B/CTA -> 2 CTAs/SM.
#define SM_HDR  2048
#define PITCH   144
#define STG_SZ  36864
#define SMEM_DYN (SM_HDR + 3 * STG_SZ)

// ---------------- fused init + convert + gate --------------------------------
// Launched as 1024 blocks x 256 threads = 8192 warps: warp w gates token w
// (identical FP sequence to the standalone k_gate), then all threads run the
// elementwise fp32->fp16 convert + out-zero loops.
__global__ void k_split(const float* __restrict__ x, const float* __restrict__ gw,
                        const float* __restrict__ w1, const float* __restrict__ w2,
                        float4* __restrict__ out4, float* __restrict__ probs_out) {
    size_t stride = (size_t)gridDim.x * blockDim.x;
    size_t i0 = (size_t)blockIdx.x * blockDim.x + threadIdx.x;
    if (i0 < E_EXP) g_cnt[i0] = 0;

    // ---- gating: one warp per token ----
    {
        int warp = (int)(i0 >> 5);
        int lane = threadIdx.x & 31;
        if (warp < T_TOK) {
            const float* xr = x + (size_t)warp * D_DIM;
            float acc[E_EXP];
#pragma unroll
            for (int e = 0; e < E_EXP; e++) acc[e] = 0.f;
            for (int k = lane * 4; k < D_DIM; k += 128) {
                float4 xv = *(const float4*)(xr + k);
#pragma unroll
                for (int e = 0; e < E_EXP; e++) {
                    float4 wv = *(const float4*)(gw + (size_t)e * D_DIM + k);
                    acc[e] += xv.x * wv.x + xv.y * wv.y + xv.z * wv.z + xv.w * wv.w;
                }
            }
#pragma unroll
            for (int e = 0; e < E_EXP; e++)
#pragma unroll
                for (int o = 16; o > 0; o >>= 1)
                    acc[e] += __shfl_xor_sync(0xffffffffu, acc[e], o);
            if (lane == 0) {
                float mx = acc[0];
#pragma unroll
                for (int e = 1; e < E_EXP; e++) mx = fmaxf(mx, acc[e]);
                float p[E_EXP], s = 0.f;
#pragma unroll
                for (int e = 0; e < E_EXP; e++) { p[e] = expf(acc[e] - mx); s += p[e]; }
                float inv = 1.f / s;
#pragma unroll
                for (int e = 0; e < E_EXP; e++) {
                    p[e] *= inv;
                    probs_out[(size_t)warp * E_EXP + e] = p[e];
                }
                int j0 = 0;
#pragma unroll
                for (int e = 1; e < E_EXP; e++) if (p[e] > p[j0]) j0 = e;
                int j1 = (j0 == 0) ? 1 : 0;
#pragma unroll
                for (int e = 0; e < E_EXP; e++) if (e != j0 && p[e] > p[j1]) j1 = e;
                float denom = p[j0] + p[j1] + 1e-9f;
                int s0 = atomicAdd(&g_cnt[j0], 1);
                g_tok[j0 * T_TOK + s0] = warp; g_wt[j0 * T_TOK + s0] = p[j0] / denom;
                int s1 = atomicAdd(&g_cnt[j1], 1);
                g_tok[j1 * T_TOK + s1] = warp; g_wt[j1 * T_TOK + s1] = p[j1] / denom;
            }
        }
    }

    // ---- out zero + fp32->fp16 converts ----
    const size_t no4 = (size_t)T_TOK * D_DIM / 4;
    float4 z = make_float4(0.f, 0.f, 0.f, 0.f);
    for (size_t i = i0; i < no4; i += stride) out4[i] = z;
    const size_t nx4 = (size_t)T_TOK * D_DIM / 4;
    const size_t nw4 = (size_t)E_EXP * F_DIM * D_DIM / 4;
    uint2* xo  = (uint2*)g_xh;
    uint2* w1o = (uint2*)g_w1h;
    uint2* w2o = (uint2*)g_w2h;
    for (size_t i = i0; i < nx4; i += stride) {
        float4 f = ((const float4*)x)[i];
        xo[i] = make_uint2(pack_h(__float2half_rn(f.x), __float2half_rn(f.y)),
                           pack_h(__float2half_rn(f.z), __float2half_rn(f.w)));
    }
    for (size_t i = i0; i < nw4; i += stride) {
        float4 f = ((const float4*)w1)[i];
        w1o[i] = make_uint2(pack_h(__float2half_rn(f.x), __float2half_rn(f.y)),
                            pack_h(__float2half_rn(f.z), __float2half_rn(f.w)));
    }
    for (size_t i = i0; i < nw4; i += stride) {
        float4 f = ((const float4*)w2)[i];
        w2o[i] = make_uint2(pack_h(__float2half_rn(f.x), __float2half_rn(f.y)),
                            pack_h(__float2half_rn(f.z), __float2half_rn(f.w)));
    }
}

// ---------------- inline prefix over 8 counters ------------------------------
__device__ __forceinline__ int expert_off(int e) {
    int off = 0;
#pragma unroll
    for (int i = 0; i < E_EXP - 1; ++i)
        if (i < e) off += g_cnt[i];
    return off;
}

// ---------------- GEMM core: block 128x128xk64, 8 warps, warp 32x64 ---------
#define LDM_SETUP()                                                            \
    const int lane = tid & 31, wid = tid >> 5;                                 \
    const int wm = (wid & 3) * 32, wn = (wid >> 2) * 64;                       \
    uint32_t aav[2];                                                           \
    _Pragma("unroll") for (int mt = 0; mt < 2; ++mt)                           \
        aav[mt] = sb + SM_HDR + (wm + mt * 16 + (lane & 15)) * PITCH +         \
                  ((lane >> 4) & 1) * 16;                                      \
    uint32_t bbv[4];                                                           \
    _Pragma("unroll") for (int g = 0; g < 4; ++g)                              \
        bbv[g] = sb + SM_HDR + 18432 +                                         \
            (wn + g * 16 + (lane & 7) + ((lane >> 4) & 1) * 8) * PITCH +       \
            ((lane >> 3) & 1) * 16;                                            \
    const uint32_t mbF0 = sb + 1536, mbF1 = sb + 1544, mbF2 = sb + 1552;       \
    const uint32_t mbE0 = sb + 1560, mbE1 = sb + 1568, mbE2 = sb + 1576;       \
    (void)mbF0; (void)mbF1; (void)mbF2; (void)mbE0; (void)mbE1; (void)mbE2;

// Fragment-pipelined chunk (validated R8): bit-identical per-accumulator order.
#define CHUNK(so) {                                                            \
    uint32_t Ah[2][2][4], Bh[2][4];                                            \
    LDX4(Ah[0][0], aav[0] + (so));                                             \
    LDX4(Ah[0][1], aav[1] + (so));                                             \
    LDX4(Bh[0], bbv[0] + (so));                                                \
    _Pragma("unroll") for (int kk = 0; kk < 4; ++kk) {                         \
        _Pragma("unroll") for (int g = 0; g < 4; ++g) {                        \
            const int cur = g & 1, nxt = cur ^ 1;                              \
            if (g < 3)       { LDX4(Bh[nxt], bbv[g + 1] + (so) + kk * 32); }   \
            else if (kk < 3) { LDX4(Bh[nxt], bbv[0] + (so) + (kk + 1) * 32); } \
            if (g == 0 && kk < 3) {                                            \
                LDX4(Ah[(kk + 1) & 1][0], aav[0] + (so) + (kk + 1) * 32);      \
                LDX4(Ah[(kk + 1) & 1][1], aav[1] + (so) + (kk + 1) * 32);      \
            }                                                                  \
            MMAH(acc[0][2 * g],     Ah[kk & 1][0], Bh[cur][0], Bh[cur][1]);    \
            MMAH(acc[1][2 * g],     Ah[kk & 1][1], Bh[cur][0], Bh[cur][1]);    \
            MMAH(acc[0][2 * g + 1], Ah[kk & 1][0], Bh[cur][2], Bh[cur][3]);    \
            MMAH(acc[1][2 * g + 1], Ah[kk & 1][1], Bh[cur][2], Bh[cur][3]);    \
        }                                                                      \
    }                                                                          \
}

#define ACC_INIT()                                                             \
    float acc[2][8][4];                                                        \
    _Pragma("unroll") for (int i = 0; i < 2; i++)                              \
        _Pragma("unroll") for (int j = 0; j < 8; j++)                          \
            _Pragma("unroll") for (int k = 0; k < 4; k++) acc[i][j][k] = 0.f;

// Consumer-first mbarrier ring iteration (schedule validated R12/R13).
#define MB_ITER(STAGE, cc, J, JS, PF, PE)                                      \
    if ((cc) < NC) {                                                           \
        MBAR_WAIT(mbF##J, PF);                                                 \
        CHUNK((J) * STG_SZ);                                                   \
        if (lane == 0) MB_ARRIVE(mbE##J);                                      \
        if ((cc) + 2 < NC) {                                                   \
            if ((cc) >= 1) MBAR_WAIT_RLX(mbE##JS, PE);                         \
            STAGE((cc) + 2, (JS) * STG_SZ);                                    \
            CP_ARRIVE(mbF##JS);                                                \
        }                                                                      \
    }

#define MB_LOOP(STAGE)                                                         \
    for (int cb = 0; cb < NC; cb += 6) {                                       \
        MB_ITER(STAGE, cb + 0, 0, 2, 0, 1);                                    \
        MB_ITER(STAGE, cb + 1, 1, 0, 0, 0);                                    \
        MB_ITER(STAGE, cb + 2, 2, 1, 0, 0);                                    \
        MB_ITER(STAGE, cb + 3, 0, 2, 1, 0);                                    \
        MB_ITER(STAGE, cb + 4, 1, 0, 1, 1);                                    \
        MB_ITER(STAGE, cb + 5, 2, 1, 1, 1);                                    \
    }

// ---------------- fc1: h = gelu(X[gather] @ W1e^T + b1) -> fp16 -------------
__global__ __launch_bounds__(256, 2) void k_fc1_h(const float* __restrict__ b1) {
    const int e = blockIdx.z;
    const int cnt = g_cnt[e];
    const int m0 = blockIdx.y * 128;
    if (m0 >= cnt) return;
    const int n0 = blockIdx.x * 128;

    extern __shared__ __align__(128) char smp[];
    const uint32_t sb = smem_u32(smp);
    int*   toks_s = (int*)smp;
    float* bias_s = (float*)(smp + 512);
    const int tid = threadIdx.x;
    if (tid < 128) {
        toks_s[tid] = g_tok[e * T_TOK + min(m0 + tid, cnt - 1)];
        bias_s[tid] = b1[e * F_DIM + n0 + tid];
    }
    if (tid == 0) {
#pragma unroll
        for (int j = 0; j < 3; ++j) {
            MB_INIT(sb + 1536 + j * 8, 256);  // full: all threads' cp.async
            MB_INIT(sb + 1560 + j * 8, 8);    // empty: one arrive per warp
        }
    }
    __syncthreads();

    // staging: q = tid&7 (16B quad of 128B row), r = tid>>3 (0..31), rows r+32j
    const int q = tid & 7, r = tid >> 3;
    const uint32_t dA = sb + SM_HDR + r * PITCH + q * 16;
    const uint32_t dB = dA + 18432;
    const char* xp = (const char*)g_xh;
    size_t aoff[4];
    const char* wp[4];
#pragma unroll
    for (int j = 0; j < 4; ++j) {
        aoff[j] = (size_t)toks_s[r + 32 * j] * (D_DIM * 2) + q * 16;
        wp[j] = (const char*)(g_w1h + ((size_t)e * F_DIM + n0 + r + 32 * j) * D_DIM) + q * 16;
    }

#define STAGE1(c, so) { const uint32_t ko = (uint32_t)(c) * 128;               \
    _Pragma("unroll") for (int j = 0; j < 4; ++j) {                            \
        CP16(dA + (so) + j * (32 * PITCH), xp + aoff[j] + ko);                 \
        CP16(dB + (so) + j * (32 * PITCH), wp[j] + ko);                        \
    } }

    LDM_SETUP();
    ACC_INIT();

    const int NC = D_DIM / 64;  // 16
    STAGE1(0, 0);          CP_ARRIVE(mbF0);
    STAGE1(1, STG_SZ);     CP_ARRIVE(mbF1);
    MB_LOOP(STAGE1);

    // epilogue: bias + exact gelu -> fp16 -> g_hh
    const int gid2 = lane >> 2, tg = lane & 3;
    const int hbase = expert_off(e) + m0;
    uint32_t* gh = (uint32_t*)g_hh;
#pragma unroll
    for (int mt = 0; mt < 2; ++mt)
#pragma unroll
        for (int nt = 0; nt < 8; ++nt) {
            const int n = wn + nt * 8 + tg * 2;
            const float bv0 = bias_s[n], bv1 = bias_s[n + 1];
#pragma unroll
            for (int h = 0; h < 2; ++h) {
                const int m = wm + mt * 16 + gid2 + h * 8;
                if (m0 + m < cnt) {
                    float v0 = acc[mt][nt][2 * h + 0] + bv0;
                    float v1 = acc[mt][nt][2 * h + 1] + bv1;
                    v0 = 0.5f * v0 * (1.f + erff(v0 * 0.7071067811865476f));
                    v1 = 0.5f * v1 * (1.f + erff(v1 * 0.7071067811865476f));
                    gh[(size_t)(hbase + m) * (F_DIM / 2) + (size_t)(n0 + n) / 2] =
                        pack_h(__float2half_rn(v0), __float2half_rn(v1));
                }
            }
        }
}

// ---------------- fc2: out[tok] += w * (H @ W2e^T + b2) ---------------------
__global__ __launch_bounds__(256, 2) void k_fc2_h(const float* __restrict__ b2,
                                                  float* __restrict__ out) {
    const int e = blockIdx.z;
    const int cnt = g_cnt[e];
    const int m0 = blockIdx.y * 128;
    if (m0 >= cnt) return;
    const int n0 = blockIdx.x * 128;

    extern __shared__ __align__(128) char smp[];
    const uint32_t sb = smem_u32(smp);
    int*   toks_s = (int*)smp;
    float* bias_s = (float*)(smp + 512);
    float* wts_s  = (float*)(smp + 1024);
    const int tid = threadIdx.x;
    if (tid < 128) {
        const int sl = min(m0 + tid, cnt - 1);
        toks_s[tid] = g_tok[e * T_TOK + sl];
        wts_s[tid]  = g_wt [e * T_TOK + sl];
        bias_s[tid] = b2[e * D_DIM + n0 + tid];
    }
    if (tid == 0) {
#pragma unroll
        for (int j = 0; j < 3; ++j) {
            MB_INIT(sb + 1536 + j * 8, 256);
            MB_INIT(sb + 1560 + j * 8, 8);
        }
    }
    __syncthreads();

    const int q = tid & 7, r = tid >> 3;
    const uint32_t dA = sb + SM_HDR + r * PITCH + q * 16;
    const uint32_t dB = dA + 18432;
    const char* hp = (const char*)g_hh;
    const int off = expert_off(e);
    size_t aoff[4];
    const char* wp[4];
#pragma unroll
    for (int j = 0; j < 4; ++j) {
        aoff[j] = (size_t)(off + min(m0 + r + 32 * j, cnt - 1)) * (F_DIM * 2) + q * 16;
        wp[j] = (const char*)(g_w2h + ((size_t)e * D_DIM + n0 + r + 32 * j) * F_DIM) + q * 16;
    }

#define STAGE2(c, so) { const uint32_t ko = (uint32_t)(c) * 128;               \
    _Pragma("unroll") for (int j = 0; j < 4; ++j) {                            \
        CP16(dA + (so) + j * (32 * PITCH), hp + aoff[j] + ko);                 \
        CP16(dB + (so) + j * (32 * PITCH), wp[j] + ko);                        \
    } }

    LDM_SETUP();
    ACC_INIT();

    const int NC = F_DIM / 64;  // 64
    STAGE2(0, 0);          CP_ARRIVE(mbF0);
    STAGE2(1, STG_SZ);     CP_ARRIVE(mbF1);
    MB_LOOP(STAGE2);

    // epilogue: (acc + bias) * wt -> atomicAdd scatter (2 adds/elem onto 0)
    const int gid2 = lane >> 2, tg = lane & 3;
#pragma unroll
    for (int mt = 0; mt < 2; ++mt)
#pragma unroll
        for (int nt = 0; nt < 8; ++nt) {
            const int n = wn + nt * 8 + tg * 2;
            const float bv0 = bias_s[n], bv1 = bias_s[n + 1];
#pragma unroll
            for (int h = 0; h < 2; ++h) {
                const int m = wm + mt * 16 + gid2 + h * 8;
                if (m0 + m < cnt) {
                    const int   t = toks_s[m];
                    const float w = wts_s[m];
                    float* op = out + (size_t)t * D_DIM + n0 + n;
                    atomicAdd(op,     (acc[mt][nt][2 * h + 0] + bv0) * w);
                    atomicAdd(op + 1, (acc[mt][nt][2 * h + 1] + bv1) * w);
                }
            }
        }
}

// ---------------- launch -----------------------------------------------------
extern "C" void kernel_launch(void* const* d_in, const int* in_sizes, int n_in,
                              void* d_out, int out_size) {
    const float* x  = (const float*)d_in[0];
    const float* gw = (const float*)d_in[1];
    const float* w1 = (const float*)d_in[2];
    const float* b1 = (const float*)d_in[3];
    const float* w2 = (const float*)d_in[4];
    const float* b2 = (const float*)d_in[5];
    float* out   = (float*)d_out;
    float* probs = out + (size_t)T_TOK * D_DIM;

    cudaFuncSetAttribute(k_fc1_h, cudaFuncAttributeMaxDynamicSharedMemorySize, SMEM_DYN);
    cudaFuncSetAttribute(k_fc2_h, cudaFuncAttributeMaxDynamicSharedMemorySize, SMEM_DYN);

    k_split<<<1024, 256>>>(x, gw, w1, w2, (float4*)out, probs);
    k_fc1_h<<<dim3(F_DIM / 128, T_TOK / 128, E_EXP), 256, SMEM_DYN>>>(b1);
    k_fc2_h<<<dim3(D_DIM / 128, T_TOK / 128, E_EXP), 256, SMEM_DYN>>>(b2, out);
}

// round 15
// speedup vs baseline: 1.4183x; 1.0022x over previous
#include <cuda_runtime.h>
#include <cuda_fp16.h>
#include <math.h>
#include <stdint.h>

#define T_TOK 8192
#define D_DIM 1024
#define F_DIM 4096
#define E_EXP 8

// ---------------- scratch (static device globals; no allocations) ----------
__device__ int    g_cnt[E_EXP];
__device__ int    g_tok[E_EXP * T_TOK];
__device__ float  g_wt [E_EXP * T_TOK];

__device__ __half g_xh [(size_t)T_TOK * D_DIM];
__device__ __half g_w1h[(size_t)E_EXP * F_DIM * D_DIM];
__device__ __half g_w2h[(size_t)E_EXP * D_DIM * F_DIM];
__device__ __half g_hh [(size_t)2 * T_TOK * F_DIM];

// ---------------- PTX helpers (sm_80+ features only) ------------------------
__device__ __forceinline__ uint32_t smem_u32(const void* p) {
    uint32_t a;
    asm("{ .reg .u64 t; cvta.to.shared.u64 t, %1; cvt.u32.u64 %0, t; }" : "=r"(a) : "l"(p));
    return a;
}
#define CP16(dst, src) asm volatile("cp.async.cg.shared.global [%0], [%1], 16;" :: "r"(dst), "l"(src) : "memory")
#define LDX4(r, a)                                                             \
    asm volatile("ldmatrix.sync.aligned.m8n8.x4.shared.b16 {%0,%1,%2,%3}, [%4];" \
        : "=r"((r)[0]), "=r"((r)[1]), "=r"((r)[2]), "=r"((r)[3]) : "r"(a))
#define MMAH(d, a, b0, b1)                                                     \
    asm volatile("mma.sync.aligned.m16n8k16.row.col.f32.f16.f16.f32 "          \
        "{%0,%1,%2,%3},{%4,%5,%6,%7},{%8,%9},{%0,%1,%2,%3};"                   \
        : "+f"((d)[0]), "+f"((d)[1]), "+f"((d)[2]), "+f"((d)[3])               \
        : "r"((a)[0]), "r"((a)[1]), "r"((a)[2]), "r"((a)[3]), "r"(b0), "r"(b1))

// mbarrier flow control (sm_80 mbarrier + cp.async integration)
#define MB_INIT(mb, c)  asm volatile("mbarrier.init.shared.b64 [%0], %1;" :: "r"(mb), "r"(c) : "memory")
#define MB_ARRIVE(mb)   asm volatile("mbarrier.arrive.shared.b64 _, [%0];" :: "r"(mb) : "memory")
#define CP_ARRIVE(mb)   asm volatile("cp.async.mbarrier.arrive.noinc.shared.b64 [%0];" :: "r"(mb) : "memory")
#define MBAR_WAIT(mb, par) do {                                                \
    uint32_t _m = (mb); uint32_t _p = (par); uint32_t _d;                      \
    asm volatile("{ .reg .pred p; mbarrier.try_wait.parity.acquire.cta.shared::cta.b64 p, [%1], %2; selp.b32 %0, 1, 0, p; }" \
        : "=r"(_d) : "r"(_m), "r"(_p) : "memory");                             \
    if (!_d) {                                                                 \
        asm volatile("{ .reg .pred P1; WL%=: mbarrier.try_wait.parity.acquire.cta.shared::cta.b64 P1, [%0], %1, 0x989680;" \
            " @P1 bra.uni WD%=; bra.uni WL%=; WD%=: }" :: "r"(_m), "r"(_p) : "memory"); \
    } } while (0)
// Relaxed wait: producer-side only — post-wait accesses are async-proxy.
#define MBAR_WAIT_RLX(mb, par) do {                                            \
    uint32_t _m = (mb); uint32_t _p = (par); uint32_t _d;                      \
    asm volatile("{ .reg .pred p; mbarrier.try_wait.parity.relaxed.cta.shared::cta.b64 p, [%1], %2; selp.b32 %0, 1, 0, p; }" \
        : "=r"(_d) : "r"(_m), "r"(_p) : "memory");                             \
    if (!_d) {                                                                 \
        asm volatile("{ .reg .pred P1; WL%=: mbarrier.try_wait.parity.relaxed.cta.shared::cta.b64 P1, [%0], %1, 0x989680;" \
            " @P1 bra.uni WD%=; bra.uni WL%=; WD%=: }" :: "r"(_m), "r"(_p) : "memory"); \
    } } while (0)

__device__ __forceinline__ uint32_t pack_h(__half a, __half b) {
    return ((uint32_t)__half_as_ushort(b) << 16) | __half_as_ushort(a);
}

// SMEM: toks @0 (512B), bias @512 (512B), wts @1024 (512B),
//       mbar full[3] @1536, empty[3] @1560, stages @2048.
// Stage (k-chunk 64 fp16 = 128B, pitch 144B): A @0 (128x144), B @18432.
// 3-stage ring: 2048 + 3*36864 = 112640 B/CTA -> 2 CTAs/SM.
#define SM_HDR  2048
#define PITCH   144
#define STG_SZ  36864
#define SMEM_DYN (SM_HDR + 3 * STG_SZ)
// fc1 epilogue staging pitch: 272B = 17*16 (uint4-aligned) and 68 words
// (68 mod 32 == 4) -> the 8-row x 4-word warp write pattern is conflict-free.
#define EPI_PITCH 272

// ---------------- fused init + convert + gate --------------------------------
__global__ void k_split(const float* __restrict__ x, const float* __restrict__ gw,
                        const float* __restrict__ w1, const float* __restrict__ w2,
                        float4* __restrict__ out4, float* __restrict__ probs_out) {
    size_t stride = (size_t)gridDim.x * blockDim.x;
    size_t i0 = (size_t)blockIdx.x * blockDim.x + threadIdx.x;
    if (i0 < E_EXP) g_cnt[i0] = 0;

    // ---- gating: one warp per token (identical FP sequence to R14) ----
    {
        int warp = (int)(i0 >> 5);
        int lane = threadIdx.x & 31;
        if (warp < T_TOK) {
            const float* xr = x + (size_t)warp * D_DIM;
            float acc[E_EXP];
#pragma unroll
            for (int e = 0; e < E_EXP; e++) acc[e] = 0.f;
            for (int k = lane * 4; k < D_DIM; k += 128) {
                float4 xv = *(const float4*)(xr + k);
#pragma unroll
                for (int e = 0; e < E_EXP; e++) {
                    float4 wv = *(const float4*)(gw + (size_t)e * D_DIM + k);
                    acc[e] += xv.x * wv.x + xv.y * wv.y + xv.z * wv.z + xv.w * wv.w;
                }
            }
#pragma unroll
            for (int e = 0; e < E_EXP; e++)
#pragma unroll
                for (int o = 16; o > 0; o >>= 1)
                    acc[e] += __shfl_xor_sync(0xffffffffu, acc[e], o);
            if (lane == 0) {
                float mx = acc[0];
#pragma unroll
                for (int e = 1; e < E_EXP; e++) mx = fmaxf(mx, acc[e]);
                float p[E_EXP], s = 0.f;
#pragma unroll
                for (int e = 0; e < E_EXP; e++) { p[e] = expf(acc[e] - mx); s += p[e]; }
                float inv = 1.f / s;
#pragma unroll
                for (int e = 0; e < E_EXP; e++) {
                    p[e] *= inv;
                    probs_out[(size_t)warp * E_EXP + e] = p[e];
                }
                int j0 = 0;
#pragma unroll
                for (int e = 1; e < E_EXP; e++) if (p[e] > p[j0]) j0 = e;
                int j1 = (j0 == 0) ? 1 : 0;
#pragma unroll
                for (int e = 0; e < E_EXP; e++) if (e != j0 && p[e] > p[j1]) j1 = e;
                float denom = p[j0] + p[j1] + 1e-9f;
                int s0 = atomicAdd(&g_cnt[j0], 1);
                g_tok[j0 * T_TOK + s0] = warp; g_wt[j0 * T_TOK + s0] = p[j0] / denom;
                int s1 = atomicAdd(&g_cnt[j1], 1);
                g_tok[j1 * T_TOK + s1] = warp; g_wt[j1 * T_TOK + s1] = p[j1] / denom;
            }
        }
    }

    // ---- out zero + fp32->fp16 converts, 2x unrolled for MLP ----
    const size_t no4 = (size_t)T_TOK * D_DIM / 4;
    float4 z = make_float4(0.f, 0.f, 0.f, 0.f);
    for (size_t i = i0; i < no4; i += 2 * stride) {
        out4[i] = z;
        if (i + stride < no4) out4[i + stride] = z;
    }
    const size_t nx4 = (size_t)T_TOK * D_DIM / 4;
    const size_t nw4 = (size_t)E_EXP * F_DIM * D_DIM / 4;
    uint2* xo  = (uint2*)g_xh;
    uint2* w1o = (uint2*)g_w1h;
    uint2* w2o = (uint2*)g_w2h;
#define CVT2(dst, src, n) for (size_t i = i0; i < (n); i += 2 * stride) {      \
        float4 fa = ((const float4*)(src))[i];                                 \
        float4 fb = (i + stride < (n)) ? ((const float4*)(src))[i + stride]    \
                                       : make_float4(0.f, 0.f, 0.f, 0.f);     \
        (dst)[i] = make_uint2(pack_h(__float2half_rn(fa.x), __float2half_rn(fa.y)), \
                              pack_h(__float2half_rn(fa.z), __float2half_rn(fa.w))); \
        if (i + stride < (n))                                                  \
            (dst)[i + stride] = make_uint2(                                    \
                pack_h(__float2half_rn(fb.x), __float2half_rn(fb.y)),          \
                pack_h(__float2half_rn(fb.z), __float2half_rn(fb.w)));        \
    }
    CVT2(xo,  x,  nx4);
    CVT2(w1o, w1, nw4);
    CVT2(w2o, w2, nw4);
}

// ---------------- inline prefix over 8 counters ------------------------------
__device__ __forceinline__ int expert_off(int e) {
    int off = 0;
#pragma unroll
    for (int i = 0; i < E_EXP - 1; ++i)
        if (i < e) off += g_cnt[i];
    return off;
}

// ---------------- GEMM core: block 128x128xk64, 8 warps, warp 32x64 ---------
#define LDM_SETUP()                                                            \
    const int lane = tid & 31, wid = tid >> 5;                                 \
    const int wm = (wid & 3) * 32, wn = (wid >> 2) * 64;                       \
    uint32_t aav[2];                                                           \
    _Pragma("unroll") for (int mt = 0; mt < 2; ++mt)                           \
        aav[mt] = sb + SM_HDR + (wm + mt * 16 + (lane & 15)) * PITCH +         \
                  ((lane >> 4) & 1) * 16;                                      \
    uint32_t bbv[4];                                                           \
    _Pragma("unroll") for (int g = 0; g < 4; ++g)                              \
        bbv[g] = sb + SM_HDR + 18432 +                                         \
            (wn + g * 16 + (lane & 7) + ((lane >> 4) & 1) * 8) * PITCH +       \
            ((lane >> 3) & 1) * 16;                                            \
    const uint32_t mbF0 = sb + 1536, mbF1 = sb + 1544, mbF2 = sb + 1552;       \
    const uint32_t mbE0 = sb + 1560, mbE1 = sb + 1568, mbE2 = sb + 1576;       \
    (void)mbF0; (void)mbF1; (void)mbF2; (void)mbE0; (void)mbE1; (void)mbE2;

// Fragment-pipelined chunk (validated R8): bit-identical per-accumulator order.
#define CHUNK(so) {                                                            \
    uint32_t Ah[2][2][4], Bh[2][4];                                            \
    LDX4(Ah[0][0], aav[0] + (so));                                             \
    LDX4(Ah[0][1], aav[1] + (so));                                             \
    LDX4(Bh[0], bbv[0] + (so));                                                \
    _Pragma("unroll") for (int kk = 0; kk < 4; ++kk) {                         \
        _Pragma("unroll") for (int g = 0; g < 4; ++g) {                        \
            const int cur = g & 1, nxt = cur ^ 1;                              \
            if (g < 3)       { LDX4(Bh[nxt], bbv[g + 1] + (so) + kk * 32); }   \
            else if (kk < 3) { LDX4(Bh[nxt], bbv[0] + (so) + (kk + 1) * 32); } \
            if (g == 0 && kk < 3) {                                            \
                LDX4(Ah[(kk + 1) & 1][0], aav[0] + (so) + (kk + 1) * 32);      \
                LDX4(Ah[(kk + 1) & 1][1], aav[1] + (so) + (kk + 1) * 32);      \
            }                                                                  \
            MMAH(acc[0][2 * g],     Ah[kk & 1][0], Bh[cur][0], Bh[cur][1]);    \
            MMAH(acc[1][2 * g],     Ah[kk & 1][1], Bh[cur][0], Bh[cur][1]);    \
            MMAH(acc[0][2 * g + 1], Ah[kk & 1][0], Bh[cur][2], Bh[cur][3]);    \
            MMAH(acc[1][2 * g + 1], Ah[kk & 1][1], Bh[cur][2], Bh[cur][3]);    \
        }                                                                      \
    }                                                                          \
}

#define ACC_INIT()                                                             \
    float acc[2][8][4];                                                        \
    _Pragma("unroll") for (int i = 0; i < 2; i++)                              \
        _Pragma("unroll") for (int j = 0; j < 8; j++)                          \
            _Pragma("unroll") for (int k = 0; k < 4; k++) acc[i][j][k] = 0.f;

// Consumer-first mbarrier ring iteration (schedule validated R12/R13).
#define MB_ITER(STAGE, cc, J, JS, PF, PE)                                      \
    if ((cc) < NC) {                                                           \
        MBAR_WAIT(mbF##J, PF);                                                 \
        CHUNK((J) * STG_SZ);                                                   \
        if (lane == 0) MB_ARRIVE(mbE##J);                                      \
        if ((cc) + 2 < NC) {                                                   \
            if ((cc) >= 1) MBAR_WAIT_RLX(mbE##JS, PE);                         \
            STAGE((cc) + 2, (JS) * STG_SZ);                                    \
            CP_ARRIVE(mbF##JS);                                                \
        }                                                                      \
    }

#define MB_LOOP(STAGE)                                                         \
    for (int cb = 0; cb < NC; cb += 6) {                                       \
        MB_ITER(STAGE, cb + 0, 0, 2, 0, 1);                                    \
        MB_ITER(STAGE, cb + 1, 1, 0, 0, 0);                                    \
        MB_ITER(STAGE, cb + 2, 2, 1, 0, 0);                                    \
        MB_ITER(STAGE, cb + 3, 0, 2, 1, 0);                                    \
        MB_ITER(STAGE, cb + 4, 1, 0, 1, 1);                                    \
        MB_ITER(STAGE, cb + 5, 2, 1, 1, 1);                                    \
    }

// ---------------- fc1: h = gelu(X[gather] @ W1e^T + b1) -> fp16 -------------
__global__ __launch_bounds__(256, 2) void k_fc1_h(const float* __restrict__ b1) {
    const int e = blockIdx.z;
    const int cnt = g_cnt[e];
    const int m0 = blockIdx.y * 128;
    if (m0 >= cnt) return;
    const int n0 = blockIdx.x * 128;

    extern __shared__ __align__(128) char smp[];
    const uint32_t sb = smem_u32(smp);
    int*   toks_s = (int*)smp;
    float* bias_s = (float*)(smp + 512);
    const int tid = threadIdx.x;
    if (tid < 128) {
        toks_s[tid] = g_tok[e * T_TOK + min(m0 + tid, cnt - 1)];
        bias_s[tid] = b1[e * F_DIM + n0 + tid];
    }
    if (tid == 0) {
#pragma unroll
        for (int j = 0; j < 3; ++j) {
            MB_INIT(sb + 1536 + j * 8, 256);  // full: all threads' cp.async
            MB_INIT(sb + 1560 + j * 8, 8);    // empty: one arrive per warp
        }
    }
    __syncthreads();

    // staging: q = tid&7 (16B quad of 128B row), r = tid>>3 (0..31), rows r+32j
    const int q = tid & 7, r = tid >> 3;
    const uint32_t dA = sb + SM_HDR + r * PITCH + q * 16;
    const uint32_t dB = dA + 18432;
    const char* xp = (const char*)g_xh;
    size_t aoff[4];
    const char* wp[4];
#pragma unroll
    for (int j = 0; j < 4; ++j) {
        aoff[j] = (size_t)toks_s[r + 32 * j] * (D_DIM * 2) + q * 16;
        wp[j] = (const char*)(g_w1h + ((size_t)e * F_DIM + n0 + r + 32 * j) * D_DIM) + q * 16;
    }

#define STAGE1(c, so) { const uint32_t ko = (uint32_t)(c) * 128;               \
    _Pragma("unroll") for (int j = 0; j < 4; ++j) {                            \
        CP16(dA + (so) + j * (32 * PITCH), xp + aoff[j] + ko);                 \
        CP16(dB + (so) + j * (32 * PITCH), wp[j] + ko);                        \
    } }

    LDM_SETUP();
    ACC_INIT();

    const int NC = D_DIM / 64;  // 16
    STAGE1(0, 0);          CP_ARRIVE(mbF0);
    STAGE1(1, STG_SZ);     CP_ARRIVE(mbF1);
    MB_LOOP(STAGE1);

    // epilogue: bias + exact gelu -> fp16 -> smem staging -> coalesced g_hh
    __syncthreads();  // all warps done with stage buffers; reuse stage0 region
    const int gid2 = lane >> 2, tg = lane & 3;
#pragma unroll
    for (int mt = 0; mt < 2; ++mt)
#pragma unroll
        for (int nt = 0; nt < 8; ++nt) {
            const int n = wn + nt * 8 + tg * 2;
            const float bv0 = bias_s[n], bv1 = bias_s[n + 1];
#pragma unroll
            for (int h = 0; h < 2; ++h) {
                const int m = wm + mt * 16 + gid2 + h * 8;
                float v0 = acc[mt][nt][2 * h + 0] + bv0;
                float v1 = acc[mt][nt][2 * h + 1] + bv1;
                v0 = 0.5f * v0 * (1.f + erff(v0 * 0.7071067811865476f));
                v1 = 0.5f * v1 * (1.f + erff(v1 * 0.7071067811865476f));
                *(uint32_t*)(smp + SM_HDR + m * EPI_PITCH + n * 2) =
                    pack_h(__float2half_rn(v0), __float2half_rn(v1));
            }
        }
    __syncthreads();
    const int hbase = expert_off(e) + m0;
    uint4* gh4 = (uint4*)g_hh;
    for (int idx = tid; idx < 128 * 16; idx += 256) {
        const int row = idx >> 4, col = idx & 15;
        if (m0 + row < cnt) {
            uint4 v = *(const uint4*)(smp + SM_HDR + row * EPI_PITCH + col * 16);
            gh4[((size_t)(hbase + row) * F_DIM + n0) / 8 + col] = v;
        }
    }
}

// ---------------- fc2: out[tok] += w * (H @ W2e^T + b2) ---------------------
__global__ __launch_bounds__(256, 2) void k_fc2_h(const float* __restrict__ b2,
                                                  float* __restrict__ out) {
    const int e = blockIdx.z;
    const int cnt = g_cnt[e];
    const int m0 = blockIdx.y * 128;
    if (m0 >= cnt) return;
    const int n0 = blockIdx.x * 128;

    extern __shared__ __align__(128) char smp[];
    const uint32_t sb = smem_u32(smp);
    int*   toks_s = (int*)smp;
    float* bias_s = (float*)(smp + 512);
    float* wts_s  = (float*)(smp + 1024);
    const int tid = threadIdx.x;
    if (tid < 128) {
        const int sl = min(m0 + tid, cnt - 1);
        toks_s[tid] = g_tok[e * T_TOK + sl];
        wts_s[tid]  = g_wt [e * T_TOK + sl];
        bias_s[tid] = b2[e * D_DIM + n0 + tid];
    }
    if (tid == 0) {
#pragma unroll
        for (int j = 0; j < 3; ++j) {
            MB_INIT(sb + 1536 + j * 8, 256);
            MB_INIT(sb + 1560 + j * 8, 8);
        }
    }
    __syncthreads();

    const int q = tid & 7, r = tid >> 3;
    const uint32_t dA = sb + SM_HDR + r * PITCH + q * 16;
    const uint32_t dB = dA + 18432;
    const char* hp = (const char*)g_hh;
    const int off = expert_off(e);
    size_t aoff[4];
    const char* wp[4];
#pragma unroll
    for (int j = 0; j < 4; ++j) {
        aoff[j] = (size_t)(off + min(m0 + r + 32 * j, cnt - 1)) * (F_DIM * 2) + q * 16;
        wp[j] = (const char*)(g_w2h + ((size_t)e * D_DIM + n0 + r + 32 * j) * F_DIM) + q * 16;
    }

#define STAGE2(c, so) { const uint32_t ko = (uint32_t)(c) * 128;               \
    _Pragma("unroll") for (int j = 0; j < 4; ++j) {                            \
        CP16(dA + (so) + j * (32 * PITCH), hp + aoff[j] + ko);                 \
        CP16(dB + (so) + j * (32 * PITCH), wp[j] + ko);                        \
    } }

    LDM_SETUP();
    ACC_INIT();

    const int NC = F_DIM / 64;  // 64
    STAGE2(0, 0);          CP_ARRIVE(mbF0);
    STAGE2(1, STG_SZ);     CP_ARRIVE(mbF1);
    MB_LOOP(STAGE2);

    // epilogue: (acc + bias) * wt -> atomicAdd scatter (2 adds/elem onto 0)
    const int gid2 = lane >> 2, tg = lane & 3;
#pragma unroll
    for (int mt = 0; mt < 2; ++mt)
#pragma unroll
        for (int nt = 0; nt < 8; ++nt) {
            const int n = wn + nt * 8 + tg * 2;
            const float bv0 = bias_s[n], bv1 = bias_s[n + 1];
#pragma unroll
            for (int h = 0; h < 2; ++h) {
                const int m = wm + mt * 16 + gid2 + h * 8;
                if (m0 + m < cnt) {
                    const int   t = toks_s[m];
                    const float w = wts_s[m];
                    float* op = out + (size_t)t * D_DIM + n0 + n;
                    atomicAdd(op,     (acc[mt][nt][2 * h + 0] + bv0) * w);
                    atomicAdd(op + 1, (acc[mt][nt][2 * h + 1] + bv1) * w);
                }
            }
        }
}

// ---------------- launch -----------------------------------------------------
extern "C" void kernel_launch(void* const* d_in, const int* in_sizes, int n_in,
                              void* d_out, int out_size) {
    const float* x  = (const float*)d_in[0];
    const float* gw = (const float*)d_in[1];
    const float* w1 = (const float*)d_in[2];
    const float* b1 = (const float*)d_in[3];
    const float* w2 = (const float*)d_in[4];
    const float* b2 = (const float*)d_in[5];
    float* out   = (float*)d_out;
    float* probs = out + (size_t)T_TOK * D_DIM;

    cudaFuncSetAttribute(k_fc1_h, cudaFuncAttributeMaxDynamicSharedMemorySize, SMEM_DYN);
    cudaFuncSetAttribute(k_fc2_h, cudaFuncAttributeMaxDynamicSharedMemorySize, SMEM_DYN);

    k_split<<<1024, 256>>>(x, gw, w1, w2, (float4*)out, probs);
    k_fc1_h<<<dim3(F_DIM / 128, T_TOK / 128, E_EXP), 256, SMEM_DYN>>>(b1);
    k_fc2_h<<<dim3(D_DIM / 128, T_TOK / 128, E_EXP), 256, SMEM_DYN>>>(b2, out);
}